// round 11
// baseline (speedup 1.0000x reference)
#include <cuda_runtime.h>
#include <cuda_bf16.h>
#include <math.h>
#include <float.h>
#include <stdint.h>

// ---------------- problem constants ----------------
#define BB   2
#define T0C  1024
#define TOTC 2048
#define DC   2048
#define NC   16
#define KC   8
#define HC   128
#define FC   8192
#define NHC  2048   // N*H
#define KHC  1024   // K*H
#define GC   2      // N/K

typedef __nv_bfloat16 bf16;

// ---------------- helpers ----------------
__device__ __forceinline__ uint32_t smem_to_u32(const void* p) {
    uint32_t a;
    asm("{ .reg .u64 t; cvta.to.shared.u64 t, %1; cvt.u32.u64 %0, t; }" : "=r"(a) : "l"(p));
    return a;
}
#define LDSM4(r, addr) \
    asm volatile("ldmatrix.sync.aligned.m8n8.x4.shared.b16 {%0,%1,%2,%3}, [%4];" \
        : "=r"((r)[0]), "=r"((r)[1]), "=r"((r)[2]), "=r"((r)[3]) : "r"(addr))
#define LDSM4T(r, addr) \
    asm volatile("ldmatrix.sync.aligned.m8n8.x4.trans.shared.b16 {%0,%1,%2,%3}, [%4];" \
        : "=r"((r)[0]), "=r"((r)[1]), "=r"((r)[2]), "=r"((r)[3]) : "r"(addr))
#define MMA16816(d, a, b0, b1) \
    asm volatile("mma.sync.aligned.m16n8k16.row.col.f32.bf16.bf16.f32 " \
        "{%0,%1,%2,%3},{%4,%5,%6,%7},{%8,%9},{%0,%1,%2,%3};" \
        : "+f"((d)[0]), "+f"((d)[1]), "+f"((d)[2]), "+f"((d)[3]) \
        : "r"((a)[0]), "r"((a)[1]), "r"((a)[2]), "r"((a)[3]), "r"(b0), "r"(b1))
#define CP_ASYNC16(saddr, gaddr) \
    asm volatile("cp.async.cg.shared.global [%0], [%1], 16;" :: "r"(saddr), "l"(gaddr))
#define CP_COMMIT() asm volatile("cp.async.commit_group;" ::: "memory")
#define CP_WAIT(n)  asm volatile("cp.async.wait_group %0;" :: "n"(n) : "memory")

// ---------------- scratch (device globals; no runtime alloc) ----------------
__device__ float g_qkv [(size_t)BB*TOTC*4096];   // packed q(2048)|k(1024)|v(1024)
__device__ float g_res [(size_t)BB*TOTC*DC];
__device__ float g_gate[(size_t)BB*TOTC*FC];

__device__ bf16 g_preh[(size_t)BB*TOTC*DC];
__device__ bf16 g_prel[(size_t)BB*TOTC*DC];
__device__ bf16 g_hidh[(size_t)BB*TOTC*DC];
__device__ bf16 g_hidl[(size_t)BB*TOTC*DC];
__device__ bf16 g_ench[(size_t)BB*TOTC*NHC];
__device__ bf16 g_encl[(size_t)BB*TOTC*NHC];
__device__ bf16 g_guh [(size_t)BB*TOTC*FC];
__device__ bf16 g_gul [(size_t)BB*TOTC*FC];
__device__ bf16 g_qh  [(size_t)BB*TOTC*NHC];
__device__ bf16 g_ql  [(size_t)BB*TOTC*NHC];
__device__ bf16 g_kh  [(size_t)BB*TOTC*KHC];
__device__ bf16 g_kl  [(size_t)BB*TOTC*KHC];
__device__ bf16 g_vh  [(size_t)BB*TOTC*KHC];
__device__ bf16 g_vl  [(size_t)BB*TOTC*KHC];
__device__ bf16 g_wh  [125829120];
__device__ bf16 g_wl  [125829120];

// ---------------- elementwise helpers ----------------
__device__ __forceinline__ float gelu_tanh(float x) {
    float x3 = x * x * x;
    return 0.5f * x * (1.0f + tanhf(0.7978845608028654f * (x + 0.044715f * x3)));
}
__device__ __forceinline__ void split_store(float v, bf16* h, bf16* l) {
    bf16 hh = __float2bfloat16(v);
    *h = hh;
    *l = __float2bfloat16(v - __bfloat162float(hh));
}
__device__ __forceinline__ uint32_t pack_split2(float a, float b, uint32_t& lo) {
    bf16 ha = __float2bfloat16(a), hb = __float2bfloat16(b);
    bf16 la = __float2bfloat16(a - __bfloat162float(ha));
    bf16 lb = __float2bfloat16(b - __bfloat162float(hb));
    lo = (uint32_t)__bfloat16_as_ushort(la) | ((uint32_t)__bfloat16_as_ushort(lb) << 16);
    return (uint32_t)__bfloat16_as_ushort(ha) | ((uint32_t)__bfloat16_as_ushort(hb) << 16);
}

// ---------------- fused weight conversion (job-table kernel) ----------------
#define NJOBS 14
struct CvtJobs {
    const float* src[NJOBS];
    bf16* h[NJOBS];
    bf16* l[NJOBS];
    int startblk[NJOBS + 1];
};

// each block: 256 threads x 32 elems = 8192 elems
__global__ void cvt_all_kernel(CvtJobs J)
{
    int bid = blockIdx.x;
    int j = 0;
    #pragma unroll
    for (int t = 1; t < NJOBS; ++t) if (bid >= J.startblk[t]) j = t;
    int blk_off = (bid - J.startblk[j]) * 8192;
    const float* src = J.src[j];
    bf16* h = J.h[j];
    bf16* l = J.l[j];

    float4 va[4][2];
    int idx[4];
    #pragma unroll
    for (int u = 0; u < 4; ++u) {
        idx[u] = blk_off + (u * 256 + threadIdx.x) * 8;
        va[u][0] = *(const float4*)(src + idx[u]);
        va[u][1] = *(const float4*)(src + idx[u] + 4);
    }
    #pragma unroll
    for (int u = 0; u < 4; ++u) {
        uint4 hv, lv;
        hv.x = pack_split2(va[u][0].x, va[u][0].y, lv.x);
        hv.y = pack_split2(va[u][0].z, va[u][0].w, lv.y);
        hv.z = pack_split2(va[u][1].x, va[u][1].y, lv.z);
        hv.w = pack_split2(va[u][1].z, va[u][1].w, lv.w);
        *(uint4*)(h + idx[u]) = hv;
        *(uint4*)(l + idx[u]) = lv;
    }
}

// ---------------- rmsnorm pair (both streams in one launch) ----------------
__global__ void rmsnorm2_kernel(const float* __restrict__ s0, const float* __restrict__ s1,
                                bf16* __restrict__ dsth, bf16* __restrict__ dstl,
                                const float* __restrict__ sc0, const float* __restrict__ sc1,
                                int srcmode)
{
    int istream = blockIdx.y;
    int row = blockIdx.x;               // 0 .. B*T0-1
    int b = row / T0C, t = row % T0C;
    size_t crow = (size_t)b * TOTC + (size_t)istream * T0C + t;
    const float* base = istream ? s1 : s0;
    const float* scale = istream ? sc1 : sc0;
    const float* s = base + (srcmode ? crow : (size_t)row) * DC;
    bf16* oh = dsth + crow * DC;
    bf16* ol = dstl + crow * DC;

    __shared__ float red[256];
    float ss = 0.f;
    for (int d = threadIdx.x; d < DC; d += 256) { float v = s[d]; ss += v * v; }
    red[threadIdx.x] = ss;
    __syncthreads();
    for (int st = 128; st > 0; st >>= 1) {
        if (threadIdx.x < st) red[threadIdx.x] += red[threadIdx.x + st];
        __syncthreads();
    }
    float inv = rsqrtf(red[0] * (1.0f / DC) + 1e-6f);
    for (int d = threadIdx.x; d < DC; d += 256) {
        float v = s[d] * inv * (1.0f + scale[d]);
        split_store(v, oh + d, ol + d);
    }
}

// ---------------- rope + split (smem sin/cos table) ----------------
__global__ void rope_split_kernel(const float* __restrict__ qkv, const int* __restrict__ positions,
                                  bf16* __restrict__ qh, bf16* __restrict__ ql,
                                  bf16* __restrict__ kh, bf16* __restrict__ kl,
                                  bf16* __restrict__ vh, bf16* __restrict__ vl)
{
    int row = blockIdx.x;                       // b*TOT + t
    float pos = (float)positions[row];
    const float QSCALE = 0.08838834764831845f;  // 128^-0.5
    const float* src = qkv + (size_t)row * 4096;

    __shared__ float ssn[64], scs[64];
    if (threadIdx.x < 64) {
        int j = threadIdx.x;
        float ts = powf(10000.0f, (float)j * (1.0f / 64.0f));
        float sn, cs;
        sincosf(pos / ts, &sn, &cs);
        ssn[j] = sn; scs[j] = cs;
    }
    __syncthreads();

    for (int w = threadIdx.x; w < (NC + KC) * 64; w += 256) {
        int head = w >> 6;
        int j = w & 63;
        float sn = ssn[j], cs = scs[j];
        if (head < NC) {
            float x1 = src[head * HC + j], x2 = src[head * HC + j + 64];
            size_t o = ((size_t)row * NC + head) * HC;
            split_store((x1 * cs - x2 * sn) * QSCALE, qh + o + j, ql + o + j);
            split_store((x2 * cs + x1 * sn) * QSCALE, qh + o + j + 64, ql + o + j + 64);
        } else {
            int kkh = head - NC;
            float x1 = src[2048 + kkh * HC + j], x2 = src[2048 + kkh * HC + j + 64];
            size_t o = ((size_t)row * KC + kkh) * HC;
            split_store(x1 * cs - x2 * sn, kh + o + j, kl + o + j);
            split_store(x2 * cs + x1 * sn, kh + o + j + 64, kl + o + j + 64);
        }
    }
    for (int idx = threadIdx.x; idx < KHC; idx += 256) {
        size_t o = (size_t)row * KHC + idx;
        split_store(src[3072 + idx], vh + o, vl + o);
    }
}

// ---------------- mma.sync GEMM: C = A @ W^T (+epilogue), bf16x3 split ----------------
// CTA 256x128, 512 threads, 16 warps, warp tile 64x32, GBK=32, 3 stages.
#define GBM 256
#define GBN 128
#define GBK 32
#define GSTAGES 3
#define ROWB   80
#define TILEA_B (256 * ROWB)
#define TILEW_B (128 * ROWB)
#define STAGE_B (2 * TILEA_B + 2 * TILEW_B)  // 61440
#define TC_SMEM_BYTES (GSTAGES * STAGE_B)    // 184320

__global__ __launch_bounds__(512, 1)
void gemm_tc(const bf16* __restrict__ Ah_, const bf16* __restrict__ Al_,
             const bf16* __restrict__ W0h, const bf16* __restrict__ W0l,
             const bf16* __restrict__ W1h, const bf16* __restrict__ W1l,
             float* __restrict__ C_, int Kd, int ldC, int epi,
             const float* __restrict__ R0, const float* __restrict__ R1,
             int resmode, int outmode,
             const float* __restrict__ G_, bf16* __restrict__ GH_, bf16* __restrict__ GL_)
{
    extern __shared__ char smem[];
    const uint32_t s0 = smem_to_u32(smem);

    const int tid = threadIdx.x;
    const int lane = tid & 31, warp = tid >> 5;
    const int wm = warp >> 2, wn = warp & 3;

    const int z = blockIdx.z, i = z >> 1, b = z & 1;
    const size_t arow0 = (size_t)b * TOTC + (size_t)i * T0C;
    const bf16* Ah = Ah_ + arow0 * Kd;
    const bf16* Al = Al_ + arow0 * Kd;
    const bf16* Wh = i ? W1h : W0h;
    const bf16* Wl = i ? W1l : W0l;
    float* C = (outmode == 0) ? (C_ + arow0 * (size_t)ldC)
                              : (C_ + ((size_t)i * BB * T0C + (size_t)b * T0C) * (size_t)ldC);
    const float* R = 0;
    if (epi == 2) R = (resmode == 0) ? ((i ? R1 : R0) + (size_t)b * T0C * ldC)
                                     : (R0 + arow0 * (size_t)ldC);
    const float* G = 0; bf16* GH = 0; bf16* GL = 0;
    if (epi == 3) { G = G_ + arow0 * (size_t)ldC; GH = GH_ + arow0 * (size_t)ldC; GL = GL_ + arow0 * (size_t)ldC; }

    const int m0 = blockIdx.y * GBM, n0 = blockIdx.x * GBN;
    const int nk = Kd / GBK;

    #define ISSUE_STAGE(cc) do {                                                 \
        int kk0 = (cc) * GBK;                                                    \
        uint32_t sbase = s0 + ((cc) % GSTAGES) * STAGE_B;                        \
        _Pragma("unroll")                                                        \
        for (int it = 0; it < 6; ++it) {                                         \
            int idx = tid + it * 512;                                            \
            const bf16* gp; uint32_t sa;                                         \
            if (idx < 2048) {                                                    \
                int tt = idx >> 10;                                              \
                int cid = idx & 1023;                                            \
                int row = cid >> 2, ch = cid & 3;                                \
                sa = sbase + tt * TILEA_B + row * ROWB + ch * 16;                \
                gp = (tt ? Al : Ah) + (size_t)(m0 + row) * Kd + kk0 + ch * 8;    \
            } else {                                                             \
                int cid = idx - 2048;                                            \
                int tt = cid >> 9;                                               \
                cid &= 511;                                                      \
                int row = cid >> 2, ch = cid & 3;                                \
                sa = sbase + 2 * TILEA_B + tt * TILEW_B + row * ROWB + ch * 16;  \
                gp = (tt ? Wl : Wh) + (size_t)(n0 + row) * Kd + kk0 + ch * 8;    \
            }                                                                    \
            CP_ASYNC16(sa, gp);                                                  \
        }                                                                        \
        CP_COMMIT();                                                             \
    } while (0)

    float acc[4][4][4];
    #pragma unroll
    for (int mf = 0; mf < 4; ++mf)
        #pragma unroll
        for (int nf = 0; nf < 4; ++nf)
            #pragma unroll
            for (int r = 0; r < 4; ++r) acc[mf][nf][r] = 0.f;

    const int a_row = wm * 64 + (lane & 15);
    const int a_cj  = lane >> 4;
    const int b_row = wn * 32 + (lane & 7) + ((lane >> 4) & 1) * 8;
    const int b_cj  = (lane >> 3) & 1;

    ISSUE_STAGE(0);
    ISSUE_STAGE(1);

    for (int c = 0; c < nk; ++c) {
        if (c + 1 < nk) CP_WAIT(1); else CP_WAIT(0);
        __syncthreads();

        uint32_t sbase = s0 + (c % GSTAGES) * STAGE_B;
        uint32_t aH = sbase, aL = sbase + TILEA_B;
        uint32_t bH = sbase + 2 * TILEA_B, bL = bH + TILEW_B;

        #pragma unroll
        for (int ks = 0; ks < 2; ++ks) {
            uint32_t aoff = (uint32_t)(a_row * ROWB + (ks * 2 + a_cj) * 16);
            uint32_t boff = (uint32_t)(b_row * ROWB + (ks * 2 + b_cj) * 16);

            uint32_t ah[4][4], bh[2][4];
            #pragma unroll
            for (int mf = 0; mf < 4; ++mf) LDSM4(ah[mf], aH + aoff + mf * (16 * ROWB));
            #pragma unroll
            for (int nf2 = 0; nf2 < 2; ++nf2) LDSM4(bh[nf2], bH + boff + nf2 * (16 * ROWB));

            #pragma unroll
            for (int nf2 = 0; nf2 < 2; ++nf2)
                #pragma unroll
                for (int mf = 0; mf < 4; ++mf) {
                    MMA16816(acc[mf][nf2 * 2],     ah[mf], bh[nf2][0], bh[nf2][1]);
                    MMA16816(acc[mf][nf2 * 2 + 1], ah[mf], bh[nf2][2], bh[nf2][3]);
                }

            if (ks == 0 && c + 2 < nk) ISSUE_STAGE(c + 2);

            uint32_t al[4][4];
            #pragma unroll
            for (int mf = 0; mf < 4; ++mf) LDSM4(al[mf], aL + aoff + mf * (16 * ROWB));
            #pragma unroll
            for (int nf2 = 0; nf2 < 2; ++nf2)
                #pragma unroll
                for (int mf = 0; mf < 4; ++mf) {
                    MMA16816(acc[mf][nf2 * 2],     al[mf], bh[nf2][0], bh[nf2][1]);
                    MMA16816(acc[mf][nf2 * 2 + 1], al[mf], bh[nf2][2], bh[nf2][3]);
                }

            uint32_t bl[2][4];
            #pragma unroll
            for (int nf2 = 0; nf2 < 2; ++nf2) LDSM4(bl[nf2], bL + boff + nf2 * (16 * ROWB));
            #pragma unroll
            for (int nf2 = 0; nf2 < 2; ++nf2)
                #pragma unroll
                for (int mf = 0; mf < 4; ++mf) {
                    MMA16816(acc[mf][nf2 * 2],     ah[mf], bl[nf2][0], bl[nf2][1]);
                    MMA16816(acc[mf][nf2 * 2 + 1], ah[mf], bl[nf2][2], bl[nf2][3]);
                }
        }
    }

    // epilogue
    #pragma unroll
    for (int mf = 0; mf < 4; ++mf) {
        int r0 = m0 + wm * 64 + mf * 16 + (lane >> 2);
        #pragma unroll
        for (int nf = 0; nf < 4; ++nf) {
            int col = n0 + wn * 32 + nf * 8 + (lane & 3) * 2;
            float2 v0 = make_float2(acc[mf][nf][0], acc[mf][nf][1]);
            float2 v1 = make_float2(acc[mf][nf][2], acc[mf][nf][3]);
            if (epi == 3) {
                float2 g0 = *(const float2*)(G + (size_t)r0 * ldC + col);
                float2 g1 = *(const float2*)(G + (size_t)(r0 + 8) * ldC + col);
                uint32_t lo0, lo1;
                uint32_t hi0 = pack_split2(v0.x * g0.x, v0.y * g0.y, lo0);
                uint32_t hi1 = pack_split2(v1.x * g1.x, v1.y * g1.y, lo1);
                *(uint32_t*)((char*)GH + ((size_t)r0 * ldC + col) * 2)       = hi0;
                *(uint32_t*)((char*)GL + ((size_t)r0 * ldC + col) * 2)       = lo0;
                *(uint32_t*)((char*)GH + ((size_t)(r0 + 8) * ldC + col) * 2) = hi1;
                *(uint32_t*)((char*)GL + ((size_t)(r0 + 8) * ldC + col) * 2) = lo1;
            } else {
                if (epi == 1) {
                    v0.x = gelu_tanh(v0.x); v0.y = gelu_tanh(v0.y);
                    v1.x = gelu_tanh(v1.x); v1.y = gelu_tanh(v1.y);
                } else if (epi == 2) {
                    float2 r4a = *(const float2*)(R + (size_t)r0 * ldC + col);
                    float2 r4b = *(const float2*)(R + (size_t)(r0 + 8) * ldC + col);
                    v0.x += r4a.x; v0.y += r4a.y;
                    v1.x += r4b.x; v1.y += r4b.y;
                }
                *(float2*)(C + (size_t)r0 * ldC + col)       = v0;
                *(float2*)(C + (size_t)(r0 + 8) * ldC + col) = v1;
            }
        }
    }
}

// ---------------- attention: mma.sync flash kernel, bf16 hi/lo splits ----------------
#define ATT_BM 128
#define ATT_BN 32
#define QROWB 272
#define KROWB 272
#define PROWB 80
#define SQH 0
#define SQL 34816
#define SKV 69632
#define KVTILE 8704
#define SPH 139264
#define SPL 149504
#define ATT_SMEM 159744
#define NEGA (-1e30f)

__global__ __launch_bounds__(256, 1)
void attn_mma_kernel(const bf16* __restrict__ qh, const bf16* __restrict__ ql,
                     const bf16* __restrict__ kh, const bf16* __restrict__ kl,
                     const bf16* __restrict__ vh, const bf16* __restrict__ vl,
                     bf16* __restrict__ ench, bf16* __restrict__ encl)
{
    extern __shared__ char smem[];
    const uint32_t s0u = smem_to_u32(smem);
    const int tid = threadIdx.x, lane = tid & 31, w = tid >> 5;
    const int bq = blockIdx.z;
    const int n = blockIdx.y;
    const int kk = n >> 1;
    const int t0 = ((int)gridDim.x - 1 - (int)blockIdx.x) * ATT_BM;
    const size_t bT = (size_t)bq * TOTC;

    #pragma unroll
    for (int it = 0; it < 16; ++it) {
        int idx = tid + it * 256;
        int tens = idx >> 11, row = (idx >> 4) & 127, ch = idx & 15;
        const bf16* src = (tens ? ql : qh) + ((bT + t0 + row) * NC + n) * HC + ch * 8;
        CP_ASYNC16(s0u + (tens ? SQL : SQH) + row * QROWB + ch * 16, src);
    }
    CP_COMMIT();

    #define LOAD_KV(j) do {                                                        \
        int _bf = (j) & 1; int _s0 = (j) * ATT_BN;                                 \
        _Pragma("unroll")                                                          \
        for (int it = 0; it < 8; ++it) {                                           \
            int idx = tid + it * 256;                                              \
            int tt = idx >> 9, cid = idx & 511, row = cid >> 4, ch = cid & 15;     \
            const bf16* srcp;                                                      \
            if (tt == 0) srcp = kh; else if (tt == 1) srcp = kl;                   \
            else if (tt == 2) srcp = vh; else srcp = vl;                           \
            srcp += ((bT + _s0 + row) * KC + kk) * HC + ch * 8;                    \
            CP_ASYNC16(s0u + SKV + (_bf * 4 + tt) * KVTILE + row * KROWB + ch * 16, srcp); \
        }                                                                          \
        CP_COMMIT();                                                               \
    } while (0)

    const int nb = t0 / ATT_BN + 4;
    LOAD_KV(0);

    const int tw = t0 + w * 16;
    const int r0 = lane >> 2;
    float oacc[16][4];
    #pragma unroll
    for (int a = 0; a < 16; ++a) { oacc[a][0] = oacc[a][1] = oacc[a][2] = oacc[a][3] = 0.f; }
    float mrow0 = NEGA, mrow1 = NEGA, lrow0 = 0.f, lrow1 = 0.f;

    const uint32_t psh_base = s0u + SPH + (w * 16) * PROWB;
    const uint32_t psl_base = s0u + SPL + (w * 16) * PROWB;

    for (int j = 0; j < nb; ++j) {
        CP_WAIT(0);
        __syncthreads();
        if (j + 1 < nb) LOAD_KV(j + 1);

        const int sblk = j * ATT_BN;
        const int bf = j & 1;
        const uint32_t kH = s0u + SKV + (bf * 4 + 0) * KVTILE;
        const uint32_t kL = s0u + SKV + (bf * 4 + 1) * KVTILE;
        const uint32_t vH = s0u + SKV + (bf * 4 + 2) * KVTILE;
        const uint32_t vL = s0u + SKV + (bf * 4 + 3) * KVTILE;

        if (sblk <= tw + 15) {
            float sacc[4][4];
            #pragma unroll
            for (int nf = 0; nf < 4; ++nf) { sacc[nf][0]=sacc[nf][1]=sacc[nf][2]=sacc[nf][3]=0.f; }
            const uint32_t aoff_base = (uint32_t)((w * 16 + (lane & 15)) * QROWB + (lane >> 4) * 16);
            const uint32_t brow = (uint32_t)((lane & 7) + ((lane >> 4) & 1) * 8);
            const uint32_t bco  = (uint32_t)(((lane >> 3) & 1) * 16);
            #pragma unroll
            for (int ks = 0; ks < 8; ++ks) {
                uint32_t ah[4], al[4], bh0[4], bh1[4], bl0[4], bl1[4];
                uint32_t aoff = aoff_base + ks * 32;
                LDSM4(ah, s0u + SQH + aoff);
                LDSM4(al, s0u + SQL + aoff);
                uint32_t boff0 = brow * KROWB + ks * 32 + bco;
                uint32_t boff1 = boff0 + 16 * KROWB;
                LDSM4(bh0, kH + boff0); LDSM4(bh1, kH + boff1);
                LDSM4(bl0, kL + boff0); LDSM4(bl1, kL + boff1);
                MMA16816(sacc[0], ah, bh0[0], bh0[1]);
                MMA16816(sacc[1], ah, bh0[2], bh0[3]);
                MMA16816(sacc[2], ah, bh1[0], bh1[1]);
                MMA16816(sacc[3], ah, bh1[2], bh1[3]);
                MMA16816(sacc[0], al, bh0[0], bh0[1]);
                MMA16816(sacc[1], al, bh0[2], bh0[3]);
                MMA16816(sacc[2], al, bh1[0], bh1[1]);
                MMA16816(sacc[3], al, bh1[2], bh1[3]);
                MMA16816(sacc[0], ah, bl0[0], bl0[1]);
                MMA16816(sacc[1], ah, bl0[2], bl0[3]);
                MMA16816(sacc[2], ah, bl1[0], bl1[1]);
                MMA16816(sacc[3], ah, bl1[2], bl1[3]);
            }

            if (sblk + ATT_BN - 1 > tw) {
                #pragma unroll
                for (int nf = 0; nf < 4; ++nf) {
                    int sg = sblk + nf * 8 + (lane & 3) * 2;
                    int tg0 = tw + r0, tg1 = tg0 + 8;
                    if (sg     > tg0) sacc[nf][0] = NEGA;
                    if (sg + 1 > tg0) sacc[nf][1] = NEGA;
                    if (sg     > tg1) sacc[nf][2] = NEGA;
                    if (sg + 1 > tg1) sacc[nf][3] = NEGA;
                }
            }

            float mx0 = NEGA, mx1 = NEGA;
            #pragma unroll
            for (int nf = 0; nf < 4; ++nf) {
                mx0 = fmaxf(mx0, fmaxf(sacc[nf][0], sacc[nf][1]));
                mx1 = fmaxf(mx1, fmaxf(sacc[nf][2], sacc[nf][3]));
            }
            mx0 = fmaxf(mx0, __shfl_xor_sync(0xffffffffu, mx0, 1));
            mx0 = fmaxf(mx0, __shfl_xor_sync(0xffffffffu, mx0, 2));
            mx1 = fmaxf(mx1, __shfl_xor_sync(0xffffffffu, mx1, 1));
            mx1 = fmaxf(mx1, __shfl_xor_sync(0xffffffffu, mx1, 2));
            float mn0 = fmaxf(mrow0, mx0), mn1 = fmaxf(mrow1, mx1);
            float al0 = __expf(mrow0 - mn0), al1 = __expf(mrow1 - mn1);
            float se0 = 0.f, se1 = 0.f;
            #pragma unroll
            for (int nf = 0; nf < 4; ++nf) {
                float p0 = __expf(sacc[nf][0] - mn0);
                float p1 = __expf(sacc[nf][1] - mn0);
                float p2 = __expf(sacc[nf][2] - mn1);
                float p3 = __expf(sacc[nf][3] - mn1);
                se0 += p0 + p1; se1 += p2 + p3;
                uint32_t pcol = (uint32_t)((nf * 8 + (lane & 3) * 2) * 2);
                uint32_t lo0, lo1;
                uint32_t hi0 = pack_split2(p0, p1, lo0);
                uint32_t hi1 = pack_split2(p2, p3, lo1);
                *(uint32_t*)(smem + (psh_base - s0u) + r0 * PROWB + pcol)       = hi0;
                *(uint32_t*)(smem + (psl_base - s0u) + r0 * PROWB + pcol)       = lo0;
                *(uint32_t*)(smem + (psh_base - s0u) + (r0 + 8) * PROWB + pcol) = hi1;
                *(uint32_t*)(smem + (psl_base - s0u) + (r0 + 8) * PROWB + pcol) = lo1;
            }
            se0 += __shfl_xor_sync(0xffffffffu, se0, 1);
            se0 += __shfl_xor_sync(0xffffffffu, se0, 2);
            se1 += __shfl_xor_sync(0xffffffffu, se1, 1);
            se1 += __shfl_xor_sync(0xffffffffu, se1, 2);
            mrow0 = mn0; mrow1 = mn1;
            lrow0 = lrow0 * al0 + se0;
            lrow1 = lrow1 * al1 + se1;
            #pragma unroll
            for (int a = 0; a < 16; ++a) {
                oacc[a][0] *= al0; oacc[a][1] *= al0;
                oacc[a][2] *= al1; oacc[a][3] *= al1;
            }
            __syncwarp();

            const uint32_t vrow = (uint32_t)((lane & 7) + ((lane >> 3) & 1) * 8);
            const uint32_t vco  = (uint32_t)((lane >> 4) * 16);
            #pragma unroll
            for (int ks2 = 0; ks2 < 2; ++ks2) {
                uint32_t ph[4], pl[4];
                uint32_t pa = (uint32_t)((lane & 15) * PROWB + (ks2 * 16 + (lane >> 4) * 8) * 2);
                LDSM4(ph, psh_base + pa);
                LDSM4(pl, psl_base + pa);
                #pragma unroll
                for (int hf = 0; hf < 8; ++hf) {
                    uint32_t bvh[4], bvl[4];
                    uint32_t voff = (ks2 * 16 + vrow) * KROWB + hf * 32 + vco;
                    LDSM4T(bvh, vH + voff);
                    LDSM4T(bvl, vL + voff);
                    MMA16816(oacc[2*hf],     ph, bvh[0], bvh[1]);
                    MMA16816(oacc[2*hf + 1], ph, bvh[2], bvh[3]);
                    MMA16816(oacc[2*hf],     pl, bvh[0], bvh[1]);
                    MMA16816(oacc[2*hf + 1], pl, bvh[2], bvh[3]);
                    MMA16816(oacc[2*hf],     ph, bvl[0], bvl[1]);
                    MMA16816(oacc[2*hf + 1], ph, bvl[2], bvl[3]);
                }
            }
        }
    }

    float inv0 = 1.0f / lrow0, inv1 = 1.0f / lrow1;
    #pragma unroll
    for (int nt = 0; nt < 16; ++nt) {
        int hcol = nt * 8 + (lane & 3) * 2;
        size_t o0 = ((bT + tw + r0) * NC + n) * HC + hcol;
        size_t o1 = ((bT + tw + r0 + 8) * NC + n) * HC + hcol;
        uint32_t lo0, lo1;
        uint32_t hi0 = pack_split2(oacc[nt][0] * inv0, oacc[nt][1] * inv0, lo0);
        uint32_t hi1 = pack_split2(oacc[nt][2] * inv1, oacc[nt][3] * inv1, lo1);
        *(uint32_t*)((char*)ench + o0 * 2) = hi0;
        *(uint32_t*)((char*)encl + o0 * 2) = lo0;
        *(uint32_t*)((char*)ench + o1 * 2) = hi1;
        *(uint32_t*)((char*)encl + o1 * 2) = lo1;
    }
}

// ---------------- host ----------------
extern "C" void kernel_launch(void* const* d_in, const int* in_sizes, int n_in,
                              void* d_out, int out_size)
{
    (void)in_sizes; (void)n_in; (void)out_size;
    const float* x0  = (const float*)d_in[0];
    const float* x1  = (const float*)d_in[1];
    const int*   pos = (const int*)  d_in[2];
    const float* q0w = (const float*)d_in[4];
    const float* q1w = (const float*)d_in[5];
    const float* k0w = (const float*)d_in[6];
    const float* k1w = (const float*)d_in[7];
    const float* v0w = (const float*)d_in[8];
    const float* v1w = (const float*)d_in[9];
    const float* o0w = (const float*)d_in[10];
    const float* o1w = (const float*)d_in[11];
    const float* gt0 = (const float*)d_in[12];
    const float* gt1 = (const float*)d_in[13];
    const float* up0 = (const float*)d_in[14];
    const float* up1 = (const float*)d_in[15];
    const float* dw0 = (const float*)d_in[16];
    const float* dw1 = (const float*)d_in[17];
    const float* pa0 = (const float*)d_in[18];
    const float* pa1 = (const float*)d_in[19];
    const float* pf0 = (const float*)d_in[20];
    const float* pf1 = (const float*)d_in[21];
    float* out = (float*)d_out;

    float *qkv, *res, *gate;
    bf16 *preh, *prel, *hidh, *hidl, *ench, *encl, *guh, *gul, *wh, *wl;
    bf16 *qhb, *qlb, *khb, *klb, *vhb, *vlb;
    cudaGetSymbolAddress((void**)&qkv,  g_qkv);
    cudaGetSymbolAddress((void**)&res,  g_res);
    cudaGetSymbolAddress((void**)&gate, g_gate);
    cudaGetSymbolAddress((void**)&preh, g_preh);
    cudaGetSymbolAddress((void**)&prel, g_prel);
    cudaGetSymbolAddress((void**)&hidh, g_hidh);
    cudaGetSymbolAddress((void**)&hidl, g_hidl);
    cudaGetSymbolAddress((void**)&ench, g_ench);
    cudaGetSymbolAddress((void**)&encl, g_encl);
    cudaGetSymbolAddress((void**)&guh,  g_guh);
    cudaGetSymbolAddress((void**)&gul,  g_gul);
    cudaGetSymbolAddress((void**)&wh,   g_wh);
    cudaGetSymbolAddress((void**)&wl,   g_wl);
    cudaGetSymbolAddress((void**)&qhb,  g_qh);
    cudaGetSymbolAddress((void**)&qlb,  g_ql);
    cudaGetSymbolAddress((void**)&khb,  g_kh);
    cudaGetSymbolAddress((void**)&klb,  g_kl);
    cudaGetSymbolAddress((void**)&vhb,  g_vh);
    cudaGetSymbolAddress((void**)&vlb,  g_vl);

    cudaFuncSetAttribute(gemm_tc, cudaFuncAttributeMaxDynamicSharedMemorySize, TC_SMEM_BYTES);
    cudaFuncSetAttribute(attn_mma_kernel, cudaFuncAttributeMaxDynamicSharedMemorySize, ATT_SMEM);

    const size_t QN   = (size_t)NHC * DC;
    const size_t KN   = (size_t)KHC * DC;
    const size_t FN   = (size_t)FC * DC;
    const size_t QKVN = QN + 2 * KN;
    const size_t oqkv0 = 0, oqkv1 = QKVN;
    const size_t oo0 = 2 * QKVN,      oo1 = oo0 + QN;
    const size_t og0 = oo1 + QN,      og1 = og0 + FN;
    const size_t ou0 = og1 + FN,      ou1 = ou0 + FN;
    const size_t od0 = ou1 + FN,      od1 = od0 + FN;

    // side stream + events, created fresh per call (host code runs only during
    // the correctness/capture calls; graph replays execute no host code).
    // Never destroyed here: destroying during an active capture is invalid.
    cudaStream_t s2;
    cudaEvent_t evFork, evJoin;
    cudaStreamCreateWithFlags(&s2, cudaStreamNonBlocking);
    cudaEventCreateWithFlags(&evFork, cudaEventDisableTiming);
    cudaEventCreateWithFlags(&evJoin, cudaEventDisableTiming);
    cudaEventRecord(evFork, 0);
    cudaStreamWaitEvent(s2, evFork, 0);

    // helper to fill a CvtJobs table
    auto fill_jobs = [&](CvtJobs& J, const float* const* srcs, const size_t* offs,
                         const size_t* lens, int njob) -> int {
        int blk = 0;
        for (int j = 0; j < NJOBS; ++j) {
            if (j < njob) {
                J.src[j] = srcs[j];
                J.h[j] = wh + offs[j];
                J.l[j] = wl + offs[j];
                J.startblk[j] = blk;
                blk += (int)(lens[j] / 8192);
            } else {
                J.src[j] = srcs[0]; J.h[j] = wh; J.l[j] = wl;
                J.startblk[j] = 0x7fffffff;
            }
        }
        J.startblk[NJOBS] = 0x7fffffff;
        return blk;
    };

    // [side stream] conversions for O/gate/up/down weights (needed from launch "O proj")
    {
        CvtJobs JB;
        const float* srcsB[8] = {o0w, o1w, gt0, gt1, up0, up1, dw0, dw1};
        const size_t offsB[8] = {oo0, oo1, og0, og1, ou0, ou1, od0, od1};
        const size_t lensB[8] = {QN, QN, FN, FN, FN, FN, FN, FN};
        int blkB = fill_jobs(JB, srcsB, offsB, lensB, 8);
        cvt_all_kernel<<<blkB, 256, 0, s2>>>(JB);
        cudaEventRecord(evJoin, s2);
    }

    // [main] QKV weight conversions (needed immediately)
    {
        CvtJobs JA;
        const float* srcsA[6] = {q0w, k0w, v0w, q1w, k1w, v1w};
        const size_t offsA[6] = {oqkv0, oqkv0 + QN, oqkv0 + QN + KN,
                                 oqkv1, oqkv1 + QN, oqkv1 + QN + KN};
        const size_t lensA[6] = {QN, KN, KN, QN, KN, KN};
        int blkA = fill_jobs(JA, srcsA, offsA, lensA, 6);
        cvt_all_kernel<<<blkA, 256>>>(JA);
    }

    // [main] pre-attn rmsnorm, both streams
    {
        dim3 g(BB * T0C, 2);
        rmsnorm2_kernel<<<g, 256>>>(x0, x1, preh, prel, pa0, pa1, 0);
    }

    // [main] QKV projection split into Q-half and KV-half
    {
        dim3 gq(2048 / GBN, T0C / GBM, 4);
        gemm_tc<<<gq, 512, TC_SMEM_BYTES>>>(preh, prel, wh + oqkv0, wl + oqkv0, wh + oqkv1, wl + oqkv1,
                                            qkv, DC, 4096, 0, 0, 0, 0, 0, 0, 0, 0);
        gemm_tc<<<gq, 512, TC_SMEM_BYTES>>>(preh, prel, wh + oqkv0 + QN, wl + oqkv0 + QN,
                                            wh + oqkv1 + QN, wl + oqkv1 + QN,
                                            qkv + 2048, DC, 4096, 0, 0, 0, 0, 0, 0, 0, 0);
    }

    // [main] RoPE + scale + split
    rope_split_kernel<<<BB * TOTC, 256>>>(qkv, pos, qhb, qlb, khb, klb, vhb, vlb);

    // [main] attention
    {
        dim3 ga(TOTC / ATT_BM, NC, BB);
        attn_mma_kernel<<<ga, 256, ATT_SMEM>>>(qhb, qlb, khb, klb, vhb, vlb, ench, encl);
    }

    // join: O/FFN weights must be converted by now
    cudaStreamWaitEvent(0, evJoin, 0);

    // [main] O projection + residual
    {
        dim3 go(DC / GBN, T0C / GBM, 4);
        gemm_tc<<<go, 512, TC_SMEM_BYTES>>>(ench, encl, wh + oo0, wl + oo0, wh + oo1, wl + oo1,
                                            res, NHC, DC, 2, x0, x1, 0, 0, 0, 0, 0);
    }

    // [main] pre-ffw rmsnorm
    {
        dim3 g(BB * T0C, 2);
        rmsnorm2_kernel<<<g, 256>>>(res, res, hidh, hidl, pf0, pf1, 1);
    }

    // [main] gate then up (fused gelu(gate)*up split)
    {
        dim3 gf(FC / GBN, T0C / GBM, 4);
        gemm_tc<<<gf, 512, TC_SMEM_BYTES>>>(hidh, hidl, wh + og0, wl + og0, wh + og1, wl + og1,
                                            gate, DC, FC, 1, 0, 0, 0, 0, 0, 0, 0);
        gemm_tc<<<gf, 512, TC_SMEM_BYTES>>>(hidh, hidl, wh + ou0, wl + ou0, wh + ou1, wl + ou1,
                                            gate, DC, FC, 3, 0, 0, 0, 0, gate, guh, gul);
    }

    // [main] down projection + residual -> out
    {
        dim3 gd(DC / GBN, T0C / GBM, 4);
        gemm_tc<<<gd, 512, TC_SMEM_BYTES>>>(guh, gul, wh + od0, wl + od0, wh + od1, wl + od1,
                                            out, FC, DC, 2, res, 0, 1, 1, 0, 0, 0);
    }
}

// round 12
// speedup vs baseline: 1.2636x; 1.2636x over previous
#include <cuda_runtime.h>
#include <cuda_bf16.h>
#include <cuda_fp16.h>
#include <math.h>
#include <float.h>
#include <stdint.h>

// ---------------- problem constants ----------------
#define BB   2
#define T0C  1024
#define TOTC 2048
#define DC   2048
#define NC   16
#define KC   8
#define HC   128
#define FC   8192
#define NHC  2048   // N*H
#define KHC  1024   // K*H
#define GC   2      // N/K

typedef __nv_bfloat16 bf16;
typedef __half fp16;

// ---------------- helpers ----------------
__device__ __forceinline__ uint32_t smem_to_u32(const void* p) {
    uint32_t a;
    asm("{ .reg .u64 t; cvta.to.shared.u64 t, %1; cvt.u32.u64 %0, t; }" : "=r"(a) : "l"(p));
    return a;
}
#define LDSM4(r, addr) \
    asm volatile("ldmatrix.sync.aligned.m8n8.x4.shared.b16 {%0,%1,%2,%3}, [%4];" \
        : "=r"((r)[0]), "=r"((r)[1]), "=r"((r)[2]), "=r"((r)[3]) : "r"(addr))
#define LDSM4T(r, addr) \
    asm volatile("ldmatrix.sync.aligned.m8n8.x4.trans.shared.b16 {%0,%1,%2,%3}, [%4];" \
        : "=r"((r)[0]), "=r"((r)[1]), "=r"((r)[2]), "=r"((r)[3]) : "r"(addr))
#define MMA16816(d, a, b0, b1) \
    asm volatile("mma.sync.aligned.m16n8k16.row.col.f32.bf16.bf16.f32 " \
        "{%0,%1,%2,%3},{%4,%5,%6,%7},{%8,%9},{%0,%1,%2,%3};" \
        : "+f"((d)[0]), "+f"((d)[1]), "+f"((d)[2]), "+f"((d)[3]) \
        : "r"((a)[0]), "r"((a)[1]), "r"((a)[2]), "r"((a)[3]), "r"(b0), "r"(b1))
#define MMAF16(d, a, b0, b1) \
    asm volatile("mma.sync.aligned.m16n8k16.row.col.f32.f16.f16.f32 " \
        "{%0,%1,%2,%3},{%4,%5,%6,%7},{%8,%9},{%0,%1,%2,%3};" \
        : "+f"((d)[0]), "+f"((d)[1]), "+f"((d)[2]), "+f"((d)[3]) \
        : "r"((a)[0]), "r"((a)[1]), "r"((a)[2]), "r"((a)[3]), "r"(b0), "r"(b1))
#define CP_ASYNC16(saddr, gaddr) \
    asm volatile("cp.async.cg.shared.global [%0], [%1], 16;" :: "r"(saddr), "l"(gaddr))
#define CP_COMMIT() asm volatile("cp.async.commit_group;" ::: "memory")
#define CP_WAIT(n)  asm volatile("cp.async.wait_group %0;" :: "n"(n) : "memory")

// ---------------- scratch (device globals; no runtime alloc) ----------------
__device__ float g_qkv [(size_t)BB*TOTC*4096];   // packed q(2048)|k(1024)|v(1024)
__device__ float g_res [(size_t)BB*TOTC*DC];
__device__ float g_gate[(size_t)BB*TOTC*FC];

__device__ bf16 g_preh[(size_t)BB*TOTC*DC];
__device__ bf16 g_prel[(size_t)BB*TOTC*DC];
__device__ bf16 g_ench[(size_t)BB*TOTC*NHC];
__device__ bf16 g_encl[(size_t)BB*TOTC*NHC];
__device__ bf16 g_qh  [(size_t)BB*TOTC*NHC];
__device__ bf16 g_ql  [(size_t)BB*TOTC*NHC];
__device__ bf16 g_kh  [(size_t)BB*TOTC*KHC];
__device__ bf16 g_kl  [(size_t)BB*TOTC*KHC];
__device__ bf16 g_vh  [(size_t)BB*TOTC*KHC];
__device__ bf16 g_vl  [(size_t)BB*TOTC*KHC];
__device__ bf16 g_wh  [25165824];   // bf16 hi: qkv0|qkv1|o0|o1
__device__ bf16 g_wl  [25165824];   // bf16 lo

__device__ fp16 g_hidh[(size_t)BB*TOTC*DC];
__device__ fp16 g_hidl[(size_t)BB*TOTC*DC];
__device__ fp16 g_guh [(size_t)BB*TOTC*FC];
__device__ fp16 g_gul [(size_t)BB*TOTC*FC];
__device__ fp16 g_wf  [100663296];  // fp16 single: gt0|gt1|up0|up1|dw0|dw1 (6 x FN)

// ---------------- elementwise helpers ----------------
__device__ __forceinline__ float gelu_tanh(float x) {
    float x3 = x * x * x;
    return 0.5f * x * (1.0f + tanhf(0.7978845608028654f * (x + 0.044715f * x3)));
}
__device__ __forceinline__ void split_store(float v, bf16* h, bf16* l) {
    bf16 hh = __float2bfloat16(v);
    *h = hh;
    *l = __float2bfloat16(v - __bfloat162float(hh));
}
__device__ __forceinline__ uint32_t pack_split2(float a, float b, uint32_t& lo) {
    bf16 ha = __float2bfloat16(a), hb = __float2bfloat16(b);
    bf16 la = __float2bfloat16(a - __bfloat162float(ha));
    bf16 lb = __float2bfloat16(b - __bfloat162float(hb));
    lo = (uint32_t)__bfloat16_as_ushort(la) | ((uint32_t)__bfloat16_as_ushort(lb) << 16);
    return (uint32_t)__bfloat16_as_ushort(ha) | ((uint32_t)__bfloat16_as_ushort(hb) << 16);
}
__device__ __forceinline__ void split_store_f16(float v, fp16* h, fp16* l) {
    fp16 hh = __float2half_rn(v);
    *h = hh;
    *l = __float2half_rn(v - __half2float(hh));
}
__device__ __forceinline__ uint32_t pack_split2_f16(float a, float b, uint32_t& lo) {
    fp16 ha = __float2half_rn(a), hb = __float2half_rn(b);
    fp16 la = __float2half_rn(a - __half2float(ha));
    fp16 lb = __float2half_rn(b - __half2float(hb));
    lo = (uint32_t)__half_as_ushort(la) | ((uint32_t)__half_as_ushort(lb) << 16);
    return (uint32_t)__half_as_ushort(ha) | ((uint32_t)__half_as_ushort(hb) << 16);
}
__device__ __forceinline__ uint32_t pack2h(float a, float b) {
    __half2 h = __floats2half2_rn(a, b);
    return *(uint32_t*)&h;
}

// ---------------- weight conversions ----------------
#define NJOBS 8
struct CvtJobs {
    const float* src[NJOBS];
    bf16* h[NJOBS];
    bf16* l[NJOBS];
    int startblk[NJOBS + 1];
};

// bf16 hi/lo: 256 threads x 32 elems = 8192 elems/block
__global__ void cvt_all_kernel(CvtJobs J)
{
    int bid = blockIdx.x;
    int j = 0;
    #pragma unroll
    for (int t = 1; t < NJOBS; ++t) if (bid >= J.startblk[t]) j = t;
    int blk_off = (bid - J.startblk[j]) * 8192;
    const float* src = J.src[j];
    bf16* h = J.h[j];
    bf16* l = J.l[j];

    float4 va[4][2];
    int idx[4];
    #pragma unroll
    for (int u = 0; u < 4; ++u) {
        idx[u] = blk_off + (u * 256 + threadIdx.x) * 8;
        va[u][0] = *(const float4*)(src + idx[u]);
        va[u][1] = *(const float4*)(src + idx[u] + 4);
    }
    #pragma unroll
    for (int u = 0; u < 4; ++u) {
        uint4 hv, lv;
        hv.x = pack_split2(va[u][0].x, va[u][0].y, lv.x);
        hv.y = pack_split2(va[u][0].z, va[u][0].w, lv.y);
        hv.z = pack_split2(va[u][1].x, va[u][1].y, lv.z);
        hv.w = pack_split2(va[u][1].z, va[u][1].w, lv.w);
        *(uint4*)(h + idx[u]) = hv;
        *(uint4*)(l + idx[u]) = lv;
    }
}

// fp16 single: 6 equal jobs of FN elems each; 8192 elems/block
struct CvtF16Jobs { const float* src[6]; fp16* dst[6]; };
__global__ void cvt_f16_kernel(CvtF16Jobs J, int blk_per_job)
{
    int j = blockIdx.x / blk_per_job;
    int blk_off = (blockIdx.x - j * blk_per_job) * 8192;
    const float* src = J.src[j];
    fp16* dst = J.dst[j];

    float4 va[4][2];
    int idx[4];
    #pragma unroll
    for (int u = 0; u < 4; ++u) {
        idx[u] = blk_off + (u * 256 + threadIdx.x) * 8;
        va[u][0] = *(const float4*)(src + idx[u]);
        va[u][1] = *(const float4*)(src + idx[u] + 4);
    }
    #pragma unroll
    for (int u = 0; u < 4; ++u) {
        uint4 o;
        o.x = pack2h(va[u][0].x, va[u][0].y);
        o.y = pack2h(va[u][0].z, va[u][0].w);
        o.z = pack2h(va[u][1].x, va[u][1].y);
        o.w = pack2h(va[u][1].z, va[u][1].w);
        *(uint4*)(dst + idx[u]) = o;
    }
}

// ---------------- rmsnorm pairs ----------------
__global__ void rmsnorm2_kernel(const float* __restrict__ s0, const float* __restrict__ s1,
                                bf16* __restrict__ dsth, bf16* __restrict__ dstl,
                                const float* __restrict__ sc0, const float* __restrict__ sc1,
                                int srcmode)
{
    int istream = blockIdx.y;
    int row = blockIdx.x;
    int b = row / T0C, t = row % T0C;
    size_t crow = (size_t)b * TOTC + (size_t)istream * T0C + t;
    const float* base = istream ? s1 : s0;
    const float* scale = istream ? sc1 : sc0;
    const float* s = base + (srcmode ? crow : (size_t)row) * DC;
    bf16* oh = dsth + crow * DC;
    bf16* ol = dstl + crow * DC;

    __shared__ float red[256];
    float ss = 0.f;
    for (int d = threadIdx.x; d < DC; d += 256) { float v = s[d]; ss += v * v; }
    red[threadIdx.x] = ss;
    __syncthreads();
    for (int st = 128; st > 0; st >>= 1) {
        if (threadIdx.x < st) red[threadIdx.x] += red[threadIdx.x + st];
        __syncthreads();
    }
    float inv = rsqrtf(red[0] * (1.0f / DC) + 1e-6f);
    for (int d = threadIdx.x; d < DC; d += 256) {
        float v = s[d] * inv * (1.0f + scale[d]);
        split_store(v, oh + d, ol + d);
    }
}

__global__ void rmsnorm2_f16_kernel(const float* __restrict__ s0,
                                    fp16* __restrict__ dsth, fp16* __restrict__ dstl,
                                    const float* __restrict__ sc0, const float* __restrict__ sc1)
{
    int istream = blockIdx.y;
    int row = blockIdx.x;
    int b = row / T0C, t = row % T0C;
    size_t crow = (size_t)b * TOTC + (size_t)istream * T0C + t;
    const float* scale = istream ? sc1 : sc0;
    const float* s = s0 + crow * DC;      // concat src
    fp16* oh = dsth + crow * DC;
    fp16* ol = dstl + crow * DC;

    __shared__ float red[256];
    float ss = 0.f;
    for (int d = threadIdx.x; d < DC; d += 256) { float v = s[d]; ss += v * v; }
    red[threadIdx.x] = ss;
    __syncthreads();
    for (int st = 128; st > 0; st >>= 1) {
        if (threadIdx.x < st) red[threadIdx.x] += red[threadIdx.x + st];
        __syncthreads();
    }
    float inv = rsqrtf(red[0] * (1.0f / DC) + 1e-6f);
    for (int d = threadIdx.x; d < DC; d += 256) {
        float v = s[d] * inv * (1.0f + scale[d]);
        split_store_f16(v, oh + d, ol + d);
    }
}

// ---------------- rope + split ----------------
__global__ void rope_split_kernel(const float* __restrict__ qkv, const int* __restrict__ positions,
                                  bf16* __restrict__ qh, bf16* __restrict__ ql,
                                  bf16* __restrict__ kh, bf16* __restrict__ kl,
                                  bf16* __restrict__ vh, bf16* __restrict__ vl)
{
    int row = blockIdx.x;
    float pos = (float)positions[row];
    const float QSCALE = 0.08838834764831845f;
    const float* src = qkv + (size_t)row * 4096;

    __shared__ float ssn[64], scs[64];
    if (threadIdx.x < 64) {
        int j = threadIdx.x;
        float ts = powf(10000.0f, (float)j * (1.0f / 64.0f));
        float sn, cs;
        sincosf(pos / ts, &sn, &cs);
        ssn[j] = sn; scs[j] = cs;
    }
    __syncthreads();

    for (int w = threadIdx.x; w < (NC + KC) * 64; w += 256) {
        int head = w >> 6;
        int j = w & 63;
        float sn = ssn[j], cs = scs[j];
        if (head < NC) {
            float x1 = src[head * HC + j], x2 = src[head * HC + j + 64];
            size_t o = ((size_t)row * NC + head) * HC;
            split_store((x1 * cs - x2 * sn) * QSCALE, qh + o + j, ql + o + j);
            split_store((x2 * cs + x1 * sn) * QSCALE, qh + o + j + 64, ql + o + j + 64);
        } else {
            int kkh = head - NC;
            float x1 = src[2048 + kkh * HC + j], x2 = src[2048 + kkh * HC + j + 64];
            size_t o = ((size_t)row * KC + kkh) * HC;
            split_store(x1 * cs - x2 * sn, kh + o + j, kl + o + j);
            split_store(x2 * cs + x1 * sn, kh + o + j + 64, kl + o + j + 64);
        }
    }
    for (int idx = threadIdx.x; idx < KHC; idx += 256) {
        size_t o = (size_t)row * KHC + idx;
        split_store(src[3072 + idx], vh + o, vl + o);
    }
}

// ---------------- shared GEMM geometry ----------------
#define GBM 256
#define GBN 128
#define GBK 32
#define GSTAGES 3
#define ROWB   80
#define TILEA_B (256 * ROWB)
#define TILEW_B (128 * ROWB)
#define STAGE_B (2 * TILEA_B + 2 * TILEW_B)  // 61440 (bf16x3)
#define TC_SMEM_BYTES (GSTAGES * STAGE_B)    // 184320
#define STAGE_F (2 * TILEA_B + TILEW_B)      // 51200 (fp16x2)
#define TC_SMEM_F (GSTAGES * STAGE_F)        // 153600

// ---------------- bf16x3 GEMM (QKV / O projections) ----------------
__global__ __launch_bounds__(512, 1)
void gemm_tc(const bf16* __restrict__ Ah_, const bf16* __restrict__ Al_,
             const bf16* __restrict__ W0h, const bf16* __restrict__ W0l,
             const bf16* __restrict__ W1h, const bf16* __restrict__ W1l,
             float* __restrict__ C_, int Kd, int ldC, int epi,
             const float* __restrict__ R0, const float* __restrict__ R1)
{
    extern __shared__ char smem[];
    const uint32_t s0 = smem_to_u32(smem);

    const int tid = threadIdx.x;
    const int lane = tid & 31, warp = tid >> 5;
    const int wm = warp >> 2, wn = warp & 3;

    const int z = blockIdx.z, i = z >> 1, b = z & 1;
    const size_t arow0 = (size_t)b * TOTC + (size_t)i * T0C;
    const bf16* Ah = Ah_ + arow0 * Kd;
    const bf16* Al = Al_ + arow0 * Kd;
    const bf16* Wh = i ? W1h : W0h;
    const bf16* Wl = i ? W1l : W0l;
    float* C = C_ + arow0 * (size_t)ldC;
    const float* R = 0;
    if (epi == 2) R = (i ? R1 : R0) + (size_t)b * T0C * ldC;

    const int m0 = blockIdx.y * GBM, n0 = blockIdx.x * GBN;
    const int nk = Kd / GBK;

    #define ISSUE_STAGE(cc) do {                                                 \
        int kk0 = (cc) * GBK;                                                    \
        uint32_t sbase = s0 + ((cc) % GSTAGES) * STAGE_B;                        \
        _Pragma("unroll")                                                        \
        for (int it = 0; it < 6; ++it) {                                         \
            int idx = tid + it * 512;                                            \
            const bf16* gp; uint32_t sa;                                         \
            if (idx < 2048) {                                                    \
                int tt = idx >> 10;                                              \
                int cid = idx & 1023;                                            \
                int row = cid >> 2, ch = cid & 3;                                \
                sa = sbase + tt * TILEA_B + row * ROWB + ch * 16;                \
                gp = (tt ? Al : Ah) + (size_t)(m0 + row) * Kd + kk0 + ch * 8;    \
            } else {                                                             \
                int cid = idx - 2048;                                            \
                int tt = cid >> 9;                                               \
                cid &= 511;                                                      \
                int row = cid >> 2, ch = cid & 3;                                \
                sa = sbase + 2 * TILEA_B + tt * TILEW_B + row * ROWB + ch * 16;  \
                gp = (tt ? Wl : Wh) + (size_t)(n0 + row) * Kd + kk0 + ch * 8;    \
            }                                                                    \
            CP_ASYNC16(sa, gp);                                                  \
        }                                                                        \
        CP_COMMIT();                                                             \
    } while (0)

    float acc[4][4][4];
    #pragma unroll
    for (int mf = 0; mf < 4; ++mf)
        #pragma unroll
        for (int nf = 0; nf < 4; ++nf)
            #pragma unroll
            for (int r = 0; r < 4; ++r) acc[mf][nf][r] = 0.f;

    const int a_row = wm * 64 + (lane & 15);
    const int a_cj  = lane >> 4;
    const int b_row = wn * 32 + (lane & 7) + ((lane >> 4) & 1) * 8;
    const int b_cj  = (lane >> 3) & 1;

    ISSUE_STAGE(0);
    ISSUE_STAGE(1);

    for (int c = 0; c < nk; ++c) {
        if (c + 1 < nk) CP_WAIT(1); else CP_WAIT(0);
        __syncthreads();

        uint32_t sbase = s0 + (c % GSTAGES) * STAGE_B;
        uint32_t aH = sbase, aL = sbase + TILEA_B;
        uint32_t bH = sbase + 2 * TILEA_B, bL = bH + TILEW_B;

        #pragma unroll
        for (int ks = 0; ks < 2; ++ks) {
            uint32_t aoff = (uint32_t)(a_row * ROWB + (ks * 2 + a_cj) * 16);
            uint32_t boff = (uint32_t)(b_row * ROWB + (ks * 2 + b_cj) * 16);

            uint32_t ah[4][4], bh[2][4];
            #pragma unroll
            for (int mf = 0; mf < 4; ++mf) LDSM4(ah[mf], aH + aoff + mf * (16 * ROWB));
            #pragma unroll
            for (int nf2 = 0; nf2 < 2; ++nf2) LDSM4(bh[nf2], bH + boff + nf2 * (16 * ROWB));

            #pragma unroll
            for (int nf2 = 0; nf2 < 2; ++nf2)
                #pragma unroll
                for (int mf = 0; mf < 4; ++mf) {
                    MMA16816(acc[mf][nf2 * 2],     ah[mf], bh[nf2][0], bh[nf2][1]);
                    MMA16816(acc[mf][nf2 * 2 + 1], ah[mf], bh[nf2][2], bh[nf2][3]);
                }

            if (ks == 0 && c + 2 < nk) ISSUE_STAGE(c + 2);

            uint32_t al[4][4];
            #pragma unroll
            for (int mf = 0; mf < 4; ++mf) LDSM4(al[mf], aL + aoff + mf * (16 * ROWB));
            #pragma unroll
            for (int nf2 = 0; nf2 < 2; ++nf2)
                #pragma unroll
                for (int mf = 0; mf < 4; ++mf) {
                    MMA16816(acc[mf][nf2 * 2],     al[mf], bh[nf2][0], bh[nf2][1]);
                    MMA16816(acc[mf][nf2 * 2 + 1], al[mf], bh[nf2][2], bh[nf2][3]);
                }

            uint32_t bl[2][4];
            #pragma unroll
            for (int nf2 = 0; nf2 < 2; ++nf2) LDSM4(bl[nf2], bL + boff + nf2 * (16 * ROWB));
            #pragma unroll
            for (int nf2 = 0; nf2 < 2; ++nf2)
                #pragma unroll
                for (int mf = 0; mf < 4; ++mf) {
                    MMA16816(acc[mf][nf2 * 2],     ah[mf], bl[nf2][0], bl[nf2][1]);
                    MMA16816(acc[mf][nf2 * 2 + 1], ah[mf], bl[nf2][2], bl[nf2][3]);
                }
        }
    }

    #pragma unroll
    for (int mf = 0; mf < 4; ++mf) {
        int r0 = m0 + wm * 64 + mf * 16 + (lane >> 2);
        #pragma unroll
        for (int nf = 0; nf < 4; ++nf) {
            int col = n0 + wn * 32 + nf * 8 + (lane & 3) * 2;
            float2 v0 = make_float2(acc[mf][nf][0], acc[mf][nf][1]);
            float2 v1 = make_float2(acc[mf][nf][2], acc[mf][nf][3]);
            if (epi == 2) {
                float2 r4a = *(const float2*)(R + (size_t)(m0 + wm * 64 + mf * 16 + (lane >> 2)) * ldC - (size_t)m0 * ldC + (size_t)0);
                // recompute cleanly:
            }
            if (epi == 2) {
                const float* rrow0 = R + (size_t)(r0 - 0) * ldC;   // R indexed by concat-local rows == C rows
                float2 ra = *(const float2*)(rrow0 + col);
                float2 rb = *(const float2*)(rrow0 + 8 * ldC + col);
                v0.x += ra.x; v0.y += ra.y;
                v1.x += rb.x; v1.y += rb.y;
            }
            *(float2*)(C + (size_t)r0 * ldC + col)       = v0;
            *(float2*)(C + (size_t)(r0 + 8) * ldC + col) = v1;
        }
    }
}

// ---------------- fp16x2 GEMM (FFN: gate / up / down) ----------------
// A fp16 hi/lo, W single fp16 per stream. epi: 1 gelu->C, 2 +residual->C, 3 gate-mul-split->GH/GL
__global__ __launch_bounds__(512, 1)
void gemm_f16(const fp16* __restrict__ Ah_, const fp16* __restrict__ Al_,
              const fp16* __restrict__ W0, const fp16* __restrict__ W1,
              float* __restrict__ C_, int Kd, int ldC, int epi,
              const float* __restrict__ R0, int outmode,
              const float* __restrict__ G_, fp16* __restrict__ GH_, fp16* __restrict__ GL_)
{
    extern __shared__ char smem[];
    const uint32_t s0 = smem_to_u32(smem);

    const int tid = threadIdx.x;
    const int lane = tid & 31, warp = tid >> 5;
    const int wm = warp >> 2, wn = warp & 3;

    const int z = blockIdx.z, i = z >> 1, b = z & 1;
    const size_t arow0 = (size_t)b * TOTC + (size_t)i * T0C;
    const fp16* Ah = Ah_ + arow0 * Kd;
    const fp16* Al = Al_ + arow0 * Kd;
    const fp16* W  = i ? W1 : W0;
    float* C = (outmode == 0) ? (C_ + arow0 * (size_t)ldC)
                              : (C_ + ((size_t)i * BB * T0C + (size_t)b * T0C) * (size_t)ldC);
    const float* R = (epi == 2) ? (R0 + arow0 * (size_t)ldC) : 0;
    const float* G = 0; fp16* GH = 0; fp16* GL = 0;
    if (epi == 3) { G = G_ + arow0 * (size_t)ldC; GH = GH_ + arow0 * (size_t)ldC; GL = GL_ + arow0 * (size_t)ldC; }

    const int m0 = blockIdx.y * GBM, n0 = blockIdx.x * GBN;
    const int nk = Kd / GBK;

    // 2560 16B chunks per stage: A(hi,lo) 2x1024, W 512. 5 per thread.
    #define ISSUE_STAGE_F(cc) do {                                               \
        int kk0 = (cc) * GBK;                                                    \
        uint32_t sbase = s0 + ((cc) % GSTAGES) * STAGE_F;                        \
        _Pragma("unroll")                                                        \
        for (int it = 0; it < 5; ++it) {                                         \
            int idx = tid + it * 512;                                            \
            const fp16* gp; uint32_t sa;                                         \
            if (idx < 2048) {                                                    \
                int tt = idx >> 10;                                              \
                int cid = idx & 1023;                                            \
                int row = cid >> 2, ch = cid & 3;                                \
                sa = sbase + tt * TILEA_B + row * ROWB + ch * 16;                \
                gp = (tt ? Al : Ah) + (size_t)(m0 + row) * Kd + kk0 + ch * 8;    \
            } else {                                                             \
                int cid = idx - 2048;                                            \
                int row = cid >> 2, ch = cid & 3;                                \
                sa = sbase + 2 * TILEA_B + row * ROWB + ch * 16;                 \
                gp = W + (size_t)(n0 + row) * Kd + kk0 + ch * 8;                 \
            }                                                                    \
            CP_ASYNC16(sa, gp);                                                  \
        }                                                                        \
        CP_COMMIT();                                                             \
    } while (0)

    float acc[4][4][4];
    #pragma unroll
    for (int mf = 0; mf < 4; ++mf)
        #pragma unroll
        for (int nf = 0; nf < 4; ++nf)
            #pragma unroll
            for (int r = 0; r < 4; ++r) acc[mf][nf][r] = 0.f;

    const int a_row = wm * 64 + (lane & 15);
    const int a_cj  = lane >> 4;
    const int b_row = wn * 32 + (lane & 7) + ((lane >> 4) & 1) * 8;
    const int b_cj  = (lane >> 3) & 1;

    ISSUE_STAGE_F(0);
    ISSUE_STAGE_F(1);

    for (int c = 0; c < nk; ++c) {
        if (c + 1 < nk) CP_WAIT(1); else CP_WAIT(0);
        __syncthreads();

        uint32_t sbase = s0 + (c % GSTAGES) * STAGE_F;
        uint32_t aH = sbase, aL = sbase + TILEA_B;
        uint32_t bB = sbase + 2 * TILEA_B;

        #pragma unroll
        for (int ks = 0; ks < 2; ++ks) {
            uint32_t aoff = (uint32_t)(a_row * ROWB + (ks * 2 + a_cj) * 16);
            uint32_t boff = (uint32_t)(b_row * ROWB + (ks * 2 + b_cj) * 16);

            uint32_t ah[4][4], bh[2][4];
            #pragma unroll
            for (int mf = 0; mf < 4; ++mf) LDSM4(ah[mf], aH + aoff + mf * (16 * ROWB));
            #pragma unroll
            for (int nf2 = 0; nf2 < 2; ++nf2) LDSM4(bh[nf2], bB + boff + nf2 * (16 * ROWB));

            // pass 1: Ah x W
            #pragma unroll
            for (int nf2 = 0; nf2 < 2; ++nf2)
                #pragma unroll
                for (int mf = 0; mf < 4; ++mf) {
                    MMAF16(acc[mf][nf2 * 2],     ah[mf], bh[nf2][0], bh[nf2][1]);
                    MMAF16(acc[mf][nf2 * 2 + 1], ah[mf], bh[nf2][2], bh[nf2][3]);
                }

            if (ks == 0 && c + 2 < nk) ISSUE_STAGE_F(c + 2);

            // pass 2: Al x W
            uint32_t al[4][4];
            #pragma unroll
            for (int mf = 0; mf < 4; ++mf) LDSM4(al[mf], aL + aoff + mf * (16 * ROWB));
            #pragma unroll
            for (int nf2 = 0; nf2 < 2; ++nf2)
                #pragma unroll
                for (int mf = 0; mf < 4; ++mf) {
                    MMAF16(acc[mf][nf2 * 2],     al[mf], bh[nf2][0], bh[nf2][1]);
                    MMAF16(acc[mf][nf2 * 2 + 1], al[mf], bh[nf2][2], bh[nf2][3]);
                }
        }
    }

    #pragma unroll
    for (int mf = 0; mf < 4; ++mf) {
        int r0 = m0 + wm * 64 + mf * 16 + (lane >> 2);
        #pragma unroll
        for (int nf = 0; nf < 4; ++nf) {
            int col = n0 + wn * 32 + nf * 8 + (lane & 3) * 2;
            float2 v0 = make_float2(acc[mf][nf][0], acc[mf][nf][1]);
            float2 v1 = make_float2(acc[mf][nf][2], acc[mf][nf][3]);
            if (epi == 3) {
                float2 g0 = *(const float2*)(G + (size_t)r0 * ldC + col);
                float2 g1 = *(const float2*)(G + (size_t)(r0 + 8) * ldC + col);
                uint32_t lo0, lo1;
                uint32_t hi0 = pack_split2_f16(v0.x * g0.x, v0.y * g0.y, lo0);
                uint32_t hi1 = pack_split2_f16(v1.x * g1.x, v1.y * g1.y, lo1);
                *(uint32_t*)((char*)GH + ((size_t)r0 * ldC + col) * 2)       = hi0;
                *(uint32_t*)((char*)GL + ((size_t)r0 * ldC + col) * 2)       = lo0;
                *(uint32_t*)((char*)GH + ((size_t)(r0 + 8) * ldC + col) * 2) = hi1;
                *(uint32_t*)((char*)GL + ((size_t)(r0 + 8) * ldC + col) * 2) = lo1;
            } else {
                if (epi == 1) {
                    v0.x = gelu_tanh(v0.x); v0.y = gelu_tanh(v0.y);
                    v1.x = gelu_tanh(v1.x); v1.y = gelu_tanh(v1.y);
                } else if (epi == 2) {
                    float2 ra = *(const float2*)(R + (size_t)r0 * ldC + col);
                    float2 rb = *(const float2*)(R + (size_t)(r0 + 8) * ldC + col);
                    v0.x += ra.x; v0.y += ra.y;
                    v1.x += rb.x; v1.y += rb.y;
                }
                *(float2*)(C + (size_t)r0 * ldC + col)       = v0;
                *(float2*)(C + (size_t)(r0 + 8) * ldC + col) = v1;
            }
        }
    }
}

// ---------------- attention: mma.sync flash kernel, bf16 hi/lo splits ----------------
#define ATT_BM 128
#define ATT_BN 32
#define QROWB 272
#define KROWB 272
#define PROWB 80
#define SQH 0
#define SQL 34816
#define SKV 69632
#define KVTILE 8704
#define SPH 139264
#define SPL 149504
#define ATT_SMEM 159744
#define NEGA (-1e30f)

__global__ __launch_bounds__(256, 1)
void attn_mma_kernel(const bf16* __restrict__ qh, const bf16* __restrict__ ql,
                     const bf16* __restrict__ kh, const bf16* __restrict__ kl,
                     const bf16* __restrict__ vh, const bf16* __restrict__ vl,
                     bf16* __restrict__ ench, bf16* __restrict__ encl)
{
    extern __shared__ char smem[];
    const uint32_t s0u = smem_to_u32(smem);
    const int tid = threadIdx.x, lane = tid & 31, w = tid >> 5;
    const int bq = blockIdx.z;
    const int n = blockIdx.y;
    const int kk = n >> 1;
    const int t0 = ((int)gridDim.x - 1 - (int)blockIdx.x) * ATT_BM;
    const size_t bT = (size_t)bq * TOTC;

    #pragma unroll
    for (int it = 0; it < 16; ++it) {
        int idx = tid + it * 256;
        int tens = idx >> 11, row = (idx >> 4) & 127, ch = idx & 15;
        const bf16* src = (tens ? ql : qh) + ((bT + t0 + row) * NC + n) * HC + ch * 8;
        CP_ASYNC16(s0u + (tens ? SQL : SQH) + row * QROWB + ch * 16, src);
    }
    CP_COMMIT();

    #define LOAD_KV(j) do {                                                        \
        int _bf = (j) & 1; int _s0 = (j) * ATT_BN;                                 \
        _Pragma("unroll")                                                          \
        for (int it = 0; it < 8; ++it) {                                           \
            int idx = tid + it * 256;                                              \
            int tt = idx >> 9, cid = idx & 511, row = cid >> 4, ch = cid & 15;     \
            const bf16* srcp;                                                      \
            if (tt == 0) srcp = kh; else if (tt == 1) srcp = kl;                   \
            else if (tt == 2) srcp = vh; else srcp = vl;                           \
            srcp += ((bT + _s0 + row) * KC + kk) * HC + ch * 8;                    \
            CP_ASYNC16(s0u + SKV + (_bf * 4 + tt) * KVTILE + row * KROWB + ch * 16, srcp); \
        }                                                                          \
        CP_COMMIT();                                                               \
    } while (0)

    const int nb = t0 / ATT_BN + 4;
    LOAD_KV(0);

    const int tw = t0 + w * 16;
    const int r0 = lane >> 2;
    float oacc[16][4];
    #pragma unroll
    for (int a = 0; a < 16; ++a) { oacc[a][0] = oacc[a][1] = oacc[a][2] = oacc[a][3] = 0.f; }
    float mrow0 = NEGA, mrow1 = NEGA, lrow0 = 0.f, lrow1 = 0.f;

    const uint32_t psh_base = s0u + SPH + (w * 16) * PROWB;
    const uint32_t psl_base = s0u + SPL + (w * 16) * PROWB;

    for (int j = 0; j < nb; ++j) {
        CP_WAIT(0);
        __syncthreads();
        if (j + 1 < nb) LOAD_KV(j + 1);

        const int sblk = j * ATT_BN;
        const int bf = j & 1;
        const uint32_t kH = s0u + SKV + (bf * 4 + 0) * KVTILE;
        const uint32_t kL = s0u + SKV + (bf * 4 + 1) * KVTILE;
        const uint32_t vH = s0u + SKV + (bf * 4 + 2) * KVTILE;
        const uint32_t vL = s0u + SKV + (bf * 4 + 3) * KVTILE;

        if (sblk <= tw + 15) {
            float sacc[4][4];
            #pragma unroll
            for (int nf = 0; nf < 4; ++nf) { sacc[nf][0]=sacc[nf][1]=sacc[nf][2]=sacc[nf][3]=0.f; }
            const uint32_t aoff_base = (uint32_t)((w * 16 + (lane & 15)) * QROWB + (lane >> 4) * 16);
            const uint32_t brow = (uint32_t)((lane & 7) + ((lane >> 4) & 1) * 8);
            const uint32_t bco  = (uint32_t)(((lane >> 3) & 1) * 16);
            #pragma unroll
            for (int ks = 0; ks < 8; ++ks) {
                uint32_t ah[4], al[4], bh0[4], bh1[4], bl0[4], bl1[4];
                uint32_t aoff = aoff_base + ks * 32;
                LDSM4(ah, s0u + SQH + aoff);
                LDSM4(al, s0u + SQL + aoff);
                uint32_t boff0 = brow * KROWB + ks * 32 + bco;
                uint32_t boff1 = boff0 + 16 * KROWB;
                LDSM4(bh0, kH + boff0); LDSM4(bh1, kH + boff1);
                LDSM4(bl0, kL + boff0); LDSM4(bl1, kL + boff1);
                MMA16816(sacc[0], ah, bh0[0], bh0[1]);
                MMA16816(sacc[1], ah, bh0[2], bh0[3]);
                MMA16816(sacc[2], ah, bh1[0], bh1[1]);
                MMA16816(sacc[3], ah, bh1[2], bh1[3]);
                MMA16816(sacc[0], al, bh0[0], bh0[1]);
                MMA16816(sacc[1], al, bh0[2], bh0[3]);
                MMA16816(sacc[2], al, bh1[0], bh1[1]);
                MMA16816(sacc[3], al, bh1[2], bh1[3]);
                MMA16816(sacc[0], ah, bl0[0], bl0[1]);
                MMA16816(sacc[1], ah, bl0[2], bl0[3]);
                MMA16816(sacc[2], ah, bl1[0], bl1[1]);
                MMA16816(sacc[3], ah, bl1[2], bl1[3]);
            }

            if (sblk + ATT_BN - 1 > tw) {
                #pragma unroll
                for (int nf = 0; nf < 4; ++nf) {
                    int sg = sblk + nf * 8 + (lane & 3) * 2;
                    int tg0 = tw + r0, tg1 = tg0 + 8;
                    if (sg     > tg0) sacc[nf][0] = NEGA;
                    if (sg + 1 > tg0) sacc[nf][1] = NEGA;
                    if (sg     > tg1) sacc[nf][2] = NEGA;
                    if (sg + 1 > tg1) sacc[nf][3] = NEGA;
                }
            }

            float mx0 = NEGA, mx1 = NEGA;
            #pragma unroll
            for (int nf = 0; nf < 4; ++nf) {
                mx0 = fmaxf(mx0, fmaxf(sacc[nf][0], sacc[nf][1]));
                mx1 = fmaxf(mx1, fmaxf(sacc[nf][2], sacc[nf][3]));
            }
            mx0 = fmaxf(mx0, __shfl_xor_sync(0xffffffffu, mx0, 1));
            mx0 = fmaxf(mx0, __shfl_xor_sync(0xffffffffu, mx0, 2));
            mx1 = fmaxf(mx1, __shfl_xor_sync(0xffffffffu, mx1, 1));
            mx1 = fmaxf(mx1, __shfl_xor_sync(0xffffffffu, mx1, 2));
            float mn0 = fmaxf(mrow0, mx0), mn1 = fmaxf(mrow1, mx1);
            float al0 = __expf(mrow0 - mn0), al1 = __expf(mrow1 - mn1);
            float se0 = 0.f, se1 = 0.f;
            #pragma unroll
            for (int nf = 0; nf < 4; ++nf) {
                float p0 = __expf(sacc[nf][0] - mn0);
                float p1 = __expf(sacc[nf][1] - mn0);
                float p2 = __expf(sacc[nf][2] - mn1);
                float p3 = __expf(sacc[nf][3] - mn1);
                se0 += p0 + p1; se1 += p2 + p3;
                uint32_t pcol = (uint32_t)((nf * 8 + (lane & 3) * 2) * 2);
                uint32_t lo0, lo1;
                uint32_t hi0 = pack_split2(p0, p1, lo0);
                uint32_t hi1 = pack_split2(p2, p3, lo1);
                *(uint32_t*)(smem + (psh_base - s0u) + r0 * PROWB + pcol)       = hi0;
                *(uint32_t*)(smem + (psl_base - s0u) + r0 * PROWB + pcol)       = lo0;
                *(uint32_t*)(smem + (psh_base - s0u) + (r0 + 8) * PROWB + pcol) = hi1;
                *(uint32_t*)(smem + (psl_base - s0u) + (r0 + 8) * PROWB + pcol) = lo1;
            }
            se0 += __shfl_xor_sync(0xffffffffu, se0, 1);
            se0 += __shfl_xor_sync(0xffffffffu, se0, 2);
            se1 += __shfl_xor_sync(0xffffffffu, se1, 1);
            se1 += __shfl_xor_sync(0xffffffffu, se1, 2);
            mrow0 = mn0; mrow1 = mn1;
            lrow0 = lrow0 * al0 + se0;
            lrow1 = lrow1 * al1 + se1;
            #pragma unroll
            for (int a = 0; a < 16; ++a) {
                oacc[a][0] *= al0; oacc[a][1] *= al0;
                oacc[a][2] *= al1; oacc[a][3] *= al1;
            }
            __syncwarp();

            const uint32_t vrow = (uint32_t)((lane & 7) + ((lane >> 3) & 1) * 8);
            const uint32_t vco  = (uint32_t)((lane >> 4) * 16);
            #pragma unroll
            for (int ks2 = 0; ks2 < 2; ++ks2) {
                uint32_t ph[4], pl[4];
                uint32_t pa = (uint32_t)((lane & 15) * PROWB + (ks2 * 16 + (lane >> 4) * 8) * 2);
                LDSM4(ph, psh_base + pa);
                LDSM4(pl, psl_base + pa);
                #pragma unroll
                for (int hf = 0; hf < 8; ++hf) {
                    uint32_t bvh[4], bvl[4];
                    uint32_t voff = (ks2 * 16 + vrow) * KROWB + hf * 32 + vco;
                    LDSM4T(bvh, vH + voff);
                    LDSM4T(bvl, vL + voff);
                    MMA16816(oacc[2*hf],     ph, bvh[0], bvh[1]);
                    MMA16816(oacc[2*hf + 1], ph, bvh[2], bvh[3]);
                    MMA16816(oacc[2*hf],     pl, bvh[0], bvh[1]);
                    MMA16816(oacc[2*hf + 1], pl, bvh[2], bvh[3]);
                    MMA16816(oacc[2*hf],     ph, bvl[0], bvl[1]);
                    MMA16816(oacc[2*hf + 1], ph, bvl[2], bvl[3]);
                }
            }
        }
    }

    float inv0 = 1.0f / lrow0, inv1 = 1.0f / lrow1;
    #pragma unroll
    for (int nt = 0; nt < 16; ++nt) {
        int hcol = nt * 8 + (lane & 3) * 2;
        size_t o0 = ((bT + tw + r0) * NC + n) * HC + hcol;
        size_t o1 = ((bT + tw + r0 + 8) * NC + n) * HC + hcol;
        uint32_t lo0, lo1;
        uint32_t hi0 = pack_split2(oacc[nt][0] * inv0, oacc[nt][1] * inv0, lo0);
        uint32_t hi1 = pack_split2(oacc[nt][2] * inv1, oacc[nt][3] * inv1, lo1);
        *(uint32_t*)((char*)ench + o0 * 2) = hi0;
        *(uint32_t*)((char*)encl + o0 * 2) = lo0;
        *(uint32_t*)((char*)ench + o1 * 2) = hi1;
        *(uint32_t*)((char*)encl + o1 * 2) = lo1;
    }
}

// ---------------- host ----------------
extern "C" void kernel_launch(void* const* d_in, const int* in_sizes, int n_in,
                              void* d_out, int out_size)
{
    (void)in_sizes; (void)n_in; (void)out_size;
    const float* x0  = (const float*)d_in[0];
    const float* x1  = (const float*)d_in[1];
    const int*   pos = (const int*)  d_in[2];
    const float* q0w = (const float*)d_in[4];
    const float* q1w = (const float*)d_in[5];
    const float* k0w = (const float*)d_in[6];
    const float* k1w = (const float*)d_in[7];
    const float* v0w = (const float*)d_in[8];
    const float* v1w = (const float*)d_in[9];
    const float* o0w = (const float*)d_in[10];
    const float* o1w = (const float*)d_in[11];
    const float* gt0 = (const float*)d_in[12];
    const float* gt1 = (const float*)d_in[13];
    const float* up0 = (const float*)d_in[14];
    const float* up1 = (const float*)d_in[15];
    const float* dw0 = (const float*)d_in[16];
    const float* dw1 = (const float*)d_in[17];
    const float* pa0 = (const float*)d_in[18];
    const float* pa1 = (const float*)d_in[19];
    const float* pf0 = (const float*)d_in[20];
    const float* pf1 = (const float*)d_in[21];
    float* out = (float*)d_out;

    float *qkv, *res, *gate;
    bf16 *preh, *prel, *ench, *encl, *wh, *wl;
    bf16 *qhb, *qlb, *khb, *klb, *vhb, *vlb;
    fp16 *hidh, *hidl, *guh, *gul, *wf;
    cudaGetSymbolAddress((void**)&qkv,  g_qkv);
    cudaGetSymbolAddress((void**)&res,  g_res);
    cudaGetSymbolAddress((void**)&gate, g_gate);
    cudaGetSymbolAddress((void**)&preh, g_preh);
    cudaGetSymbolAddress((void**)&prel, g_prel);
    cudaGetSymbolAddress((void**)&ench, g_ench);
    cudaGetSymbolAddress((void**)&encl, g_encl);
    cudaGetSymbolAddress((void**)&wh,   g_wh);
    cudaGetSymbolAddress((void**)&wl,   g_wl);
    cudaGetSymbolAddress((void**)&qhb,  g_qh);
    cudaGetSymbolAddress((void**)&qlb,  g_ql);
    cudaGetSymbolAddress((void**)&khb,  g_kh);
    cudaGetSymbolAddress((void**)&klb,  g_kl);
    cudaGetSymbolAddress((void**)&vhb,  g_vh);
    cudaGetSymbolAddress((void**)&vlb,  g_vl);
    cudaGetSymbolAddress((void**)&hidh, g_hidh);
    cudaGetSymbolAddress((void**)&hidl, g_hidl);
    cudaGetSymbolAddress((void**)&guh,  g_guh);
    cudaGetSymbolAddress((void**)&gul,  g_gul);
    cudaGetSymbolAddress((void**)&wf,   g_wf);

    cudaFuncSetAttribute(gemm_tc,  cudaFuncAttributeMaxDynamicSharedMemorySize, TC_SMEM_BYTES);
    cudaFuncSetAttribute(gemm_f16, cudaFuncAttributeMaxDynamicSharedMemorySize, TC_SMEM_F);
    cudaFuncSetAttribute(attn_mma_kernel, cudaFuncAttributeMaxDynamicSharedMemorySize, ATT_SMEM);

    const size_t QN   = (size_t)NHC * DC;     // 4194304
    const size_t KN   = (size_t)KHC * DC;     // 2097152
    const size_t FN   = (size_t)FC * DC;      // 16777216
    const size_t QKVN = QN + 2 * KN;          // 8388608
    const size_t oqkv0 = 0, oqkv1 = QKVN;
    const size_t oo0 = 2 * QKVN, oo1 = oo0 + QN;
    // fp16 weight offsets in g_wf
    const size_t fg0 = 0,       fg1 = FN;
    const size_t fu0 = 2 * FN,  fu1 = 3 * FN;
    const size_t fd0 = 4 * FN,  fd1 = 5 * FN;

    // [launch 0] bf16 hi/lo conversions (qkv + o weights)
    {
        CvtJobs J;
        const float* srcs[NJOBS] = {q0w, k0w, v0w, q1w, k1w, v1w, o0w, o1w};
        const size_t offs[NJOBS] = {oqkv0, oqkv0 + QN, oqkv0 + QN + KN,
                                    oqkv1, oqkv1 + QN, oqkv1 + QN + KN, oo0, oo1};
        const size_t lens[NJOBS] = {QN, KN, KN, QN, KN, KN, QN, QN};
        int blk = 0;
        for (int j = 0; j < NJOBS; ++j) {
            J.src[j] = srcs[j];
            J.h[j] = wh + offs[j];
            J.l[j] = wl + offs[j];
            J.startblk[j] = blk;
            blk += (int)(lens[j] / 8192);
        }
        J.startblk[NJOBS] = blk;
        cvt_all_kernel<<<blk, 256>>>(J);
    }

    // [launch 1] fp16 single conversions (gate/up/down weights)
    {
        CvtF16Jobs J;
        const float* srcs[6] = {gt0, gt1, up0, up1, dw0, dw1};
        const size_t offs[6] = {fg0, fg1, fu0, fu1, fd0, fd1};
        for (int j = 0; j < 6; ++j) { J.src[j] = srcs[j]; J.dst[j] = wf + offs[j]; }
        int bpj = (int)(FN / 8192);   // 2048
        cvt_f16_kernel<<<6 * bpj, 256>>>(J, bpj);
    }

    // [launch 2] pre-attn rmsnorm -> bf16 hi/lo
    {
        dim3 g(BB * T0C, 2);
        rmsnorm2_kernel<<<g, 256>>>(x0, x1, preh, prel, pa0, pa1, 0);
    }

    // [launches 3-4] QKV projection (Q half, KV half) — bf16x3
    {
        dim3 gq(2048 / GBN, T0C / GBM, 4);
        gemm_tc<<<gq, 512, TC_SMEM_BYTES>>>(preh, prel, wh + oqkv0, wl + oqkv0, wh + oqkv1, wl + oqkv1,
                                            qkv, DC, 4096, 0, 0, 0);
        gemm_tc<<<gq, 512, TC_SMEM_BYTES>>>(preh, prel, wh + oqkv0 + QN, wl + oqkv0 + QN,
                                            wh + oqkv1 + QN, wl + oqkv1 + QN,
                                            qkv + 2048, DC, 4096, 0, 0, 0);
    }

    // [launch 5] RoPE + scale + split
    rope_split_kernel<<<BB * TOTC, 256>>>(qkv, pos, qhb, qlb, khb, klb, vhb, vlb);

    // [launch 6] attention -> ench/encl
    {
        dim3 ga(TOTC / ATT_BM, NC, BB);
        attn_mma_kernel<<<ga, 256, ATT_SMEM>>>(qhb, qlb, khb, klb, vhb, vlb, ench, encl);
    }

    // [launch 7] O projection + residual — bf16x3
    {
        dim3 go(DC / GBN, T0C / GBM, 4);
        gemm_tc<<<go, 512, TC_SMEM_BYTES>>>(ench, encl, wh + oo0, wl + oo0, wh + oo1, wl + oo1,
                                            res, NHC, DC, 2, x0, x1);
    }

    // [launch 8] pre-ffw rmsnorm -> fp16 hi/lo
    {
        dim3 g(BB * T0C, 2);
        rmsnorm2_f16_kernel<<<g, 256>>>(res, hidh, hidl, pf0, pf1);
    }

    // [launches 9-10] gate (gelu) then up (fused gelu(gate)*up -> fp16 split) — fp16x2
    {
        dim3 gf(FC / GBN, T0C / GBM, 4);
        gemm_f16<<<gf, 512, TC_SMEM_F>>>(hidh, hidl, wf + fg0, wf + fg1,
                                         gate, DC, FC, 1, 0, 0, 0, 0, 0);
        gemm_f16<<<gf, 512, TC_SMEM_F>>>(hidh, hidl, wf + fu0, wf + fu1,
                                         gate, DC, FC, 3, 0, 0, gate, guh, gul);
    }

    // [launch 11] down projection + residual -> out (stream-major) — fp16x2
    {
        dim3 gd(DC / GBN, T0C / GBM, 4);
        gemm_f16<<<gd, 512, TC_SMEM_F>>>(guh, gul, wf + fd0, wf + fd1,
                                         out, FC, DC, 2, res, 1, 0, 0, 0);
    }
}

// round 13
// speedup vs baseline: 1.3711x; 1.0851x over previous
#include <cuda_runtime.h>
#include <cuda_bf16.h>
#include <cuda_fp16.h>
#include <math.h>
#include <float.h>
#include <stdint.h>

// ---------------- problem constants ----------------
#define BB   2
#define T0C  1024
#define TOTC 2048
#define DC   2048
#define NC   16
#define KC   8
#define HC   128
#define FC   8192
#define NHC  2048   // N*H
#define KHC  1024   // K*H
#define GC   2      // N/K

typedef __nv_bfloat16 bf16;
typedef __half fp16;

// ---------------- helpers ----------------
__device__ __forceinline__ uint32_t smem_to_u32(const void* p) {
    uint32_t a;
    asm("{ .reg .u64 t; cvta.to.shared.u64 t, %1; cvt.u32.u64 %0, t; }" : "=r"(a) : "l"(p));
    return a;
}
#define LDSM4(r, addr) \
    asm volatile("ldmatrix.sync.aligned.m8n8.x4.shared.b16 {%0,%1,%2,%3}, [%4];" \
        : "=r"((r)[0]), "=r"((r)[1]), "=r"((r)[2]), "=r"((r)[3]) : "r"(addr))
#define LDSM4T(r, addr) \
    asm volatile("ldmatrix.sync.aligned.m8n8.x4.trans.shared.b16 {%0,%1,%2,%3}, [%4];" \
        : "=r"((r)[0]), "=r"((r)[1]), "=r"((r)[2]), "=r"((r)[3]) : "r"(addr))
#define MMA16816(d, a, b0, b1) \
    asm volatile("mma.sync.aligned.m16n8k16.row.col.f32.bf16.bf16.f32 " \
        "{%0,%1,%2,%3},{%4,%5,%6,%7},{%8,%9},{%0,%1,%2,%3};" \
        : "+f"((d)[0]), "+f"((d)[1]), "+f"((d)[2]), "+f"((d)[3]) \
        : "r"((a)[0]), "r"((a)[1]), "r"((a)[2]), "r"((a)[3]), "r"(b0), "r"(b1))
#define MMAF16(d, a, b0, b1) \
    asm volatile("mma.sync.aligned.m16n8k16.row.col.f32.f16.f16.f32 " \
        "{%0,%1,%2,%3},{%4,%5,%6,%7},{%8,%9},{%0,%1,%2,%3};" \
        : "+f"((d)[0]), "+f"((d)[1]), "+f"((d)[2]), "+f"((d)[3]) \
        : "r"((a)[0]), "r"((a)[1]), "r"((a)[2]), "r"((a)[3]), "r"(b0), "r"(b1))
#define CP_ASYNC16(saddr, gaddr) \
    asm volatile("cp.async.cg.shared.global [%0], [%1], 16;" :: "r"(saddr), "l"(gaddr))
#define CP_COMMIT() asm volatile("cp.async.commit_group;" ::: "memory")
#define CP_WAIT(n)  asm volatile("cp.async.wait_group %0;" :: "n"(n) : "memory")

// ---------------- scratch (device globals; no runtime alloc) ----------------
__device__ float g_qkv [(size_t)BB*TOTC*4096];   // packed q(2048)|k(1024)|v(1024)
__device__ float g_res [(size_t)BB*TOTC*DC];
__device__ float g_gate[(size_t)BB*TOTC*FC];

__device__ bf16 g_qh  [(size_t)BB*TOTC*NHC];
__device__ bf16 g_ql  [(size_t)BB*TOTC*NHC];
__device__ bf16 g_kh  [(size_t)BB*TOTC*KHC];
__device__ bf16 g_kl  [(size_t)BB*TOTC*KHC];
__device__ bf16 g_vh  [(size_t)BB*TOTC*KHC];
__device__ bf16 g_vl  [(size_t)BB*TOTC*KHC];

__device__ fp16 g_preh[(size_t)BB*TOTC*DC];
__device__ fp16 g_prel[(size_t)BB*TOTC*DC];
__device__ fp16 g_ench[(size_t)BB*TOTC*NHC];
__device__ fp16 g_encl[(size_t)BB*TOTC*NHC];
__device__ fp16 g_hidh[(size_t)BB*TOTC*DC];
__device__ fp16 g_hidl[(size_t)BB*TOTC*DC];
__device__ fp16 g_guh [(size_t)BB*TOTC*FC];
__device__ fp16 g_gul [(size_t)BB*TOTC*FC];
__device__ fp16 g_wf  [125829120];  // fp16 weights: qkv0|qkv1|o0|o1|g0|g1|u0|u1|d0|d1

// ---------------- elementwise helpers ----------------
__device__ __forceinline__ float gelu_tanh(float x) {
    float x3 = x * x * x;
    return 0.5f * x * (1.0f + tanhf(0.7978845608028654f * (x + 0.044715f * x3)));
}
__device__ __forceinline__ void split_store(float v, bf16* h, bf16* l) {
    bf16 hh = __float2bfloat16(v);
    *h = hh;
    *l = __float2bfloat16(v - __bfloat162float(hh));
}
__device__ __forceinline__ uint32_t pack_split2(float a, float b, uint32_t& lo) {
    bf16 ha = __float2bfloat16(a), hb = __float2bfloat16(b);
    bf16 la = __float2bfloat16(a - __bfloat162float(ha));
    bf16 lb = __float2bfloat16(b - __bfloat162float(hb));
    lo = (uint32_t)__bfloat16_as_ushort(la) | ((uint32_t)__bfloat16_as_ushort(lb) << 16);
    return (uint32_t)__bfloat16_as_ushort(ha) | ((uint32_t)__bfloat16_as_ushort(hb) << 16);
}
__device__ __forceinline__ void split_store_f16(float v, fp16* h, fp16* l) {
    fp16 hh = __float2half_rn(v);
    *h = hh;
    *l = __float2half_rn(v - __half2float(hh));
}
__device__ __forceinline__ uint32_t pack_split2_f16(float a, float b, uint32_t& lo) {
    fp16 ha = __float2half_rn(a), hb = __float2half_rn(b);
    fp16 la = __float2half_rn(a - __half2float(ha));
    fp16 lb = __float2half_rn(b - __half2float(hb));
    lo = (uint32_t)__half_as_ushort(la) | ((uint32_t)__half_as_ushort(lb) << 16);
    return (uint32_t)__half_as_ushort(ha) | ((uint32_t)__half_as_ushort(hb) << 16);
}
__device__ __forceinline__ uint32_t pack2h(float a, float b) {
    __half2 h = __floats2half2_rn(a, b);
    return *(uint32_t*)&h;
}

// ---------------- weight conversion: fp16 single, 14 jobs ----------------
#define NJOBS 14
struct CvtF16Jobs {
    const float* src[NJOBS];
    fp16* dst[NJOBS];
    int startblk[NJOBS + 1];
};

// 256 threads x 32 elems = 8192 elems/block
__global__ void cvt_f16_kernel(CvtF16Jobs J)
{
    int bid = blockIdx.x;
    int j = 0;
    #pragma unroll
    for (int t = 1; t < NJOBS; ++t) if (bid >= J.startblk[t]) j = t;
    int blk_off = (bid - J.startblk[j]) * 8192;
    const float* src = J.src[j];
    fp16* dst = J.dst[j];

    float4 va[4][2];
    int idx[4];
    #pragma unroll
    for (int u = 0; u < 4; ++u) {
        idx[u] = blk_off + (u * 256 + threadIdx.x) * 8;
        va[u][0] = *(const float4*)(src + idx[u]);
        va[u][1] = *(const float4*)(src + idx[u] + 4);
    }
    #pragma unroll
    for (int u = 0; u < 4; ++u) {
        uint4 o;
        o.x = pack2h(va[u][0].x, va[u][0].y);
        o.y = pack2h(va[u][0].z, va[u][0].w);
        o.z = pack2h(va[u][1].x, va[u][1].y);
        o.w = pack2h(va[u][1].z, va[u][1].w);
        *(uint4*)(dst + idx[u]) = o;
    }
}

// ---------------- rmsnorm pair -> fp16 hi/lo ----------------
// srcmode 0: src per-stream (s0/s1, rows b*T0+t); srcmode 1: concat src s0
__global__ void rmsnorm2_f16_kernel(const float* __restrict__ s0, const float* __restrict__ s1,
                                    fp16* __restrict__ dsth, fp16* __restrict__ dstl,
                                    const float* __restrict__ sc0, const float* __restrict__ sc1,
                                    int srcmode)
{
    int istream = blockIdx.y;
    int row = blockIdx.x;
    int b = row / T0C, t = row % T0C;
    size_t crow = (size_t)b * TOTC + (size_t)istream * T0C + t;
    const float* base = istream ? s1 : s0;
    const float* scale = istream ? sc1 : sc0;
    const float* s = srcmode ? (s0 + crow * DC) : (base + (size_t)row * DC);
    fp16* oh = dsth + crow * DC;
    fp16* ol = dstl + crow * DC;

    __shared__ float red[256];
    float ss = 0.f;
    for (int d = threadIdx.x; d < DC; d += 256) { float v = s[d]; ss += v * v; }
    red[threadIdx.x] = ss;
    __syncthreads();
    for (int st = 128; st > 0; st >>= 1) {
        if (threadIdx.x < st) red[threadIdx.x] += red[threadIdx.x + st];
        __syncthreads();
    }
    float inv = rsqrtf(red[0] * (1.0f / DC) + 1e-6f);
    for (int d = threadIdx.x; d < DC; d += 256) {
        float v = s[d] * inv * (1.0f + scale[d]);
        split_store_f16(v, oh + d, ol + d);
    }
}

// ---------------- rope + split (fp32 qkv -> bf16 hi/lo q,k,v) ----------------
__global__ void rope_split_kernel(const float* __restrict__ qkv, const int* __restrict__ positions,
                                  bf16* __restrict__ qh, bf16* __restrict__ ql,
                                  bf16* __restrict__ kh, bf16* __restrict__ kl,
                                  bf16* __restrict__ vh, bf16* __restrict__ vl)
{
    int row = blockIdx.x;
    float pos = (float)positions[row];
    const float QSCALE = 0.08838834764831845f;
    const float* src = qkv + (size_t)row * 4096;

    __shared__ float ssn[64], scs[64];
    if (threadIdx.x < 64) {
        int j = threadIdx.x;
        float ts = powf(10000.0f, (float)j * (1.0f / 64.0f));
        float sn, cs;
        sincosf(pos / ts, &sn, &cs);
        ssn[j] = sn; scs[j] = cs;
    }
    __syncthreads();

    for (int w = threadIdx.x; w < (NC + KC) * 64; w += 256) {
        int head = w >> 6;
        int j = w & 63;
        float sn = ssn[j], cs = scs[j];
        if (head < NC) {
            float x1 = src[head * HC + j], x2 = src[head * HC + j + 64];
            size_t o = ((size_t)row * NC + head) * HC;
            split_store((x1 * cs - x2 * sn) * QSCALE, qh + o + j, ql + o + j);
            split_store((x2 * cs + x1 * sn) * QSCALE, qh + o + j + 64, ql + o + j + 64);
        } else {
            int kkh = head - NC;
            float x1 = src[2048 + kkh * HC + j], x2 = src[2048 + kkh * HC + j + 64];
            size_t o = ((size_t)row * KC + kkh) * HC;
            split_store(x1 * cs - x2 * sn, kh + o + j, kl + o + j);
            split_store(x2 * cs + x1 * sn, kh + o + j + 64, kl + o + j + 64);
        }
    }
    for (int idx = threadIdx.x; idx < KHC; idx += 256) {
        size_t o = (size_t)row * KHC + idx;
        split_store(src[3072 + idx], vh + o, vl + o);
    }
}

// ---------------- GEMM geometry ----------------
#define GBM 256
#define GBN 128
#define GBK 32
#define GSTAGES 3
#define ROWB   80
#define TILEA_B (256 * ROWB)
#define TILEW_B (128 * ROWB)
#define STAGE_F (2 * TILEA_B + TILEW_B)      // 51200 (fp16x2)
#define TC_SMEM_F (GSTAGES * STAGE_F)        // 153600

// ---------------- fp16x2 GEMM (all projections) ----------------
// A fp16 hi/lo, W single fp16 per stream (W0/W1 selected by stream i).
// epi: 0 plain, 1 gelu, 2 +residual, 3 gate-mul-split->GH/GL
// resmode: 0 per-stream R (R0/R1 + b*T0*ldC), 1 concat R0 (+ arow0*ldC)
// outmode: 0 concat rows, 1 stream-major rows
__global__ __launch_bounds__(512, 1)
void gemm_f16(const fp16* __restrict__ Ah_, const fp16* __restrict__ Al_,
              const fp16* __restrict__ W0, const fp16* __restrict__ W1,
              float* __restrict__ C_, int Kd, int ldC, int epi,
              const float* __restrict__ R0, const float* __restrict__ R1,
              int resmode, int outmode,
              const float* __restrict__ G_, fp16* __restrict__ GH_, fp16* __restrict__ GL_)
{
    extern __shared__ char smem[];
    const uint32_t s0 = smem_to_u32(smem);

    const int tid = threadIdx.x;
    const int lane = tid & 31, warp = tid >> 5;
    const int wm = warp >> 2, wn = warp & 3;

    const int z = blockIdx.z, i = z >> 1, b = z & 1;
    const size_t arow0 = (size_t)b * TOTC + (size_t)i * T0C;
    const fp16* Ah = Ah_ + arow0 * Kd;
    const fp16* Al = Al_ + arow0 * Kd;
    const fp16* W  = i ? W1 : W0;
    float* C = (outmode == 0) ? (C_ + arow0 * (size_t)ldC)
                              : (C_ + ((size_t)i * BB * T0C + (size_t)b * T0C) * (size_t)ldC);
    const float* R = 0;
    if (epi == 2) R = (resmode == 0) ? ((i ? R1 : R0) + (size_t)b * T0C * ldC)
                                     : (R0 + arow0 * (size_t)ldC);
    const float* G = 0; fp16* GH = 0; fp16* GL = 0;
    if (epi == 3) { G = G_ + arow0 * (size_t)ldC; GH = GH_ + arow0 * (size_t)ldC; GL = GL_ + arow0 * (size_t)ldC; }

    const int m0 = blockIdx.y * GBM, n0 = blockIdx.x * GBN;
    const int nk = Kd / GBK;

    // 2560 16B chunks per stage: A(hi,lo) 2x1024, W 512. 5 per thread.
    #define ISSUE_STAGE_F(cc) do {                                               \
        int kk0 = (cc) * GBK;                                                    \
        uint32_t sbase = s0 + ((cc) % GSTAGES) * STAGE_F;                        \
        _Pragma("unroll")                                                        \
        for (int it = 0; it < 5; ++it) {                                         \
            int idx = tid + it * 512;                                            \
            const fp16* gp; uint32_t sa;                                         \
            if (idx < 2048) {                                                    \
                int tt = idx >> 10;                                              \
                int cid = idx & 1023;                                            \
                int row = cid >> 2, ch = cid & 3;                                \
                sa = sbase + tt * TILEA_B + row * ROWB + ch * 16;                \
                gp = (tt ? Al : Ah) + (size_t)(m0 + row) * Kd + kk0 + ch * 8;    \
            } else {                                                             \
                int cid = idx - 2048;                                            \
                int row = cid >> 2, ch = cid & 3;                                \
                sa = sbase + 2 * TILEA_B + row * ROWB + ch * 16;                 \
                gp = W + (size_t)(n0 + row) * Kd + kk0 + ch * 8;                 \
            }                                                                    \
            CP_ASYNC16(sa, gp);                                                  \
        }                                                                        \
        CP_COMMIT();                                                             \
    } while (0)

    float acc[4][4][4];
    #pragma unroll
    for (int mf = 0; mf < 4; ++mf)
        #pragma unroll
        for (int nf = 0; nf < 4; ++nf)
            #pragma unroll
            for (int r = 0; r < 4; ++r) acc[mf][nf][r] = 0.f;

    const int a_row = wm * 64 + (lane & 15);
    const int a_cj  = lane >> 4;
    const int b_row = wn * 32 + (lane & 7) + ((lane >> 4) & 1) * 8;
    const int b_cj  = (lane >> 3) & 1;

    ISSUE_STAGE_F(0);
    ISSUE_STAGE_F(1);

    for (int c = 0; c < nk; ++c) {
        if (c + 1 < nk) CP_WAIT(1); else CP_WAIT(0);
        __syncthreads();

        uint32_t sbase = s0 + (c % GSTAGES) * STAGE_F;
        uint32_t aH = sbase, aL = sbase + TILEA_B;
        uint32_t bB = sbase + 2 * TILEA_B;

        #pragma unroll
        for (int ks = 0; ks < 2; ++ks) {
            uint32_t aoff = (uint32_t)(a_row * ROWB + (ks * 2 + a_cj) * 16);
            uint32_t boff = (uint32_t)(b_row * ROWB + (ks * 2 + b_cj) * 16);

            uint32_t ah[4][4], bh[2][4];
            #pragma unroll
            for (int mf = 0; mf < 4; ++mf) LDSM4(ah[mf], aH + aoff + mf * (16 * ROWB));
            #pragma unroll
            for (int nf2 = 0; nf2 < 2; ++nf2) LDSM4(bh[nf2], bB + boff + nf2 * (16 * ROWB));

            // pass 1: Ah x W
            #pragma unroll
            for (int nf2 = 0; nf2 < 2; ++nf2)
                #pragma unroll
                for (int mf = 0; mf < 4; ++mf) {
                    MMAF16(acc[mf][nf2 * 2],     ah[mf], bh[nf2][0], bh[nf2][1]);
                    MMAF16(acc[mf][nf2 * 2 + 1], ah[mf], bh[nf2][2], bh[nf2][3]);
                }

            if (ks == 0 && c + 2 < nk) ISSUE_STAGE_F(c + 2);

            // pass 2: Al x W
            uint32_t al[4][4];
            #pragma unroll
            for (int mf = 0; mf < 4; ++mf) LDSM4(al[mf], aL + aoff + mf * (16 * ROWB));
            #pragma unroll
            for (int nf2 = 0; nf2 < 2; ++nf2)
                #pragma unroll
                for (int mf = 0; mf < 4; ++mf) {
                    MMAF16(acc[mf][nf2 * 2],     al[mf], bh[nf2][0], bh[nf2][1]);
                    MMAF16(acc[mf][nf2 * 2 + 1], al[mf], bh[nf2][2], bh[nf2][3]);
                }
        }
    }

    #pragma unroll
    for (int mf = 0; mf < 4; ++mf) {
        int r0 = m0 + wm * 64 + mf * 16 + (lane >> 2);
        #pragma unroll
        for (int nf = 0; nf < 4; ++nf) {
            int col = n0 + wn * 32 + nf * 8 + (lane & 3) * 2;
            float2 v0 = make_float2(acc[mf][nf][0], acc[mf][nf][1]);
            float2 v1 = make_float2(acc[mf][nf][2], acc[mf][nf][3]);
            if (epi == 3) {
                float2 g0 = *(const float2*)(G + (size_t)r0 * ldC + col);
                float2 g1 = *(const float2*)(G + (size_t)(r0 + 8) * ldC + col);
                uint32_t lo0, lo1;
                uint32_t hi0 = pack_split2_f16(v0.x * g0.x, v0.y * g0.y, lo0);
                uint32_t hi1 = pack_split2_f16(v1.x * g1.x, v1.y * g1.y, lo1);
                *(uint32_t*)((char*)GH + ((size_t)r0 * ldC + col) * 2)       = hi0;
                *(uint32_t*)((char*)GL + ((size_t)r0 * ldC + col) * 2)       = lo0;
                *(uint32_t*)((char*)GH + ((size_t)(r0 + 8) * ldC + col) * 2) = hi1;
                *(uint32_t*)((char*)GL + ((size_t)(r0 + 8) * ldC + col) * 2) = lo1;
            } else {
                if (epi == 1) {
                    v0.x = gelu_tanh(v0.x); v0.y = gelu_tanh(v0.y);
                    v1.x = gelu_tanh(v1.x); v1.y = gelu_tanh(v1.y);
                } else if (epi == 2) {
                    float2 ra = *(const float2*)(R + (size_t)r0 * ldC + col);
                    float2 rb = *(const float2*)(R + (size_t)(r0 + 8) * ldC + col);
                    v0.x += ra.x; v0.y += ra.y;
                    v1.x += rb.x; v1.y += rb.y;
                }
                *(float2*)(C + (size_t)r0 * ldC + col)       = v0;
                *(float2*)(C + (size_t)(r0 + 8) * ldC + col) = v1;
            }
        }
    }
}

// ---------------- attention: mma.sync flash kernel, bf16 hi/lo splits ----------------
#define ATT_BM 128
#define ATT_BN 32
#define QROWB 272
#define KROWB 272
#define PROWB 80
#define SQH 0
#define SQL 34816
#define SKV 69632
#define KVTILE 8704
#define SPH 139264
#define SPL 149504
#define ATT_SMEM 159744
#define NEGA (-1e30f)

__global__ __launch_bounds__(256, 1)
void attn_mma_kernel(const bf16* __restrict__ qh, const bf16* __restrict__ ql,
                     const bf16* __restrict__ kh, const bf16* __restrict__ kl,
                     const bf16* __restrict__ vh, const bf16* __restrict__ vl,
                     fp16* __restrict__ ench, fp16* __restrict__ encl)
{
    extern __shared__ char smem[];
    const uint32_t s0u = smem_to_u32(smem);
    const int tid = threadIdx.x, lane = tid & 31, w = tid >> 5;
    const int bq = blockIdx.z;
    const int n = blockIdx.y;
    const int kk = n >> 1;
    const int t0 = ((int)gridDim.x - 1 - (int)blockIdx.x) * ATT_BM;
    const size_t bT = (size_t)bq * TOTC;

    #pragma unroll
    for (int it = 0; it < 16; ++it) {
        int idx = tid + it * 256;
        int tens = idx >> 11, row = (idx >> 4) & 127, ch = idx & 15;
        const bf16* src = (tens ? ql : qh) + ((bT + t0 + row) * NC + n) * HC + ch * 8;
        CP_ASYNC16(s0u + (tens ? SQL : SQH) + row * QROWB + ch * 16, src);
    }
    CP_COMMIT();

    #define LOAD_KV(j) do {                                                        \
        int _bf = (j) & 1; int _s0 = (j) * ATT_BN;                                 \
        _Pragma("unroll")                                                          \
        for (int it = 0; it < 8; ++it) {                                           \
            int idx = tid + it * 256;                                              \
            int tt = idx >> 9, cid = idx & 511, row = cid >> 4, ch = cid & 15;     \
            const bf16* srcp;                                                      \
            if (tt == 0) srcp = kh; else if (tt == 1) srcp = kl;                   \
            else if (tt == 2) srcp = vh; else srcp = vl;                           \
            srcp += ((bT + _s0 + row) * KC + kk) * HC + ch * 8;                    \
            CP_ASYNC16(s0u + SKV + (_bf * 4 + tt) * KVTILE + row * KROWB + ch * 16, srcp); \
        }                                                                          \
        CP_COMMIT();                                                               \
    } while (0)

    const int nb = t0 / ATT_BN + 4;
    LOAD_KV(0);

    const int tw = t0 + w * 16;
    const int r0 = lane >> 2;
    float oacc[16][4];
    #pragma unroll
    for (int a = 0; a < 16; ++a) { oacc[a][0] = oacc[a][1] = oacc[a][2] = oacc[a][3] = 0.f; }
    float mrow0 = NEGA, mrow1 = NEGA, lrow0 = 0.f, lrow1 = 0.f;

    const uint32_t psh_base = s0u + SPH + (w * 16) * PROWB;
    const uint32_t psl_base = s0u + SPL + (w * 16) * PROWB;

    for (int j = 0; j < nb; ++j) {
        CP_WAIT(0);
        __syncthreads();
        if (j + 1 < nb) LOAD_KV(j + 1);

        const int sblk = j * ATT_BN;
        const int bf = j & 1;
        const uint32_t kH = s0u + SKV + (bf * 4 + 0) * KVTILE;
        const uint32_t kL = s0u + SKV + (bf * 4 + 1) * KVTILE;
        const uint32_t vH = s0u + SKV + (bf * 4 + 2) * KVTILE;
        const uint32_t vL = s0u + SKV + (bf * 4 + 3) * KVTILE;

        if (sblk <= tw + 15) {
            float sacc[4][4];
            #pragma unroll
            for (int nf = 0; nf < 4; ++nf) { sacc[nf][0]=sacc[nf][1]=sacc[nf][2]=sacc[nf][3]=0.f; }
            const uint32_t aoff_base = (uint32_t)((w * 16 + (lane & 15)) * QROWB + (lane >> 4) * 16);
            const uint32_t brow = (uint32_t)((lane & 7) + ((lane >> 4) & 1) * 8);
            const uint32_t bco  = (uint32_t)(((lane >> 3) & 1) * 16);
            #pragma unroll
            for (int ks = 0; ks < 8; ++ks) {
                uint32_t ah[4], al[4], bh0[4], bh1[4], bl0[4], bl1[4];
                uint32_t aoff = aoff_base + ks * 32;
                LDSM4(ah, s0u + SQH + aoff);
                LDSM4(al, s0u + SQL + aoff);
                uint32_t boff0 = brow * KROWB + ks * 32 + bco;
                uint32_t boff1 = boff0 + 16 * KROWB;
                LDSM4(bh0, kH + boff0); LDSM4(bh1, kH + boff1);
                LDSM4(bl0, kL + boff0); LDSM4(bl1, kL + boff1);
                MMA16816(sacc[0], ah, bh0[0], bh0[1]);
                MMA16816(sacc[1], ah, bh0[2], bh0[3]);
                MMA16816(sacc[2], ah, bh1[0], bh1[1]);
                MMA16816(sacc[3], ah, bh1[2], bh1[3]);
                MMA16816(sacc[0], al, bh0[0], bh0[1]);
                MMA16816(sacc[1], al, bh0[2], bh0[3]);
                MMA16816(sacc[2], al, bh1[0], bh1[1]);
                MMA16816(sacc[3], al, bh1[2], bh1[3]);
                MMA16816(sacc[0], ah, bl0[0], bl0[1]);
                MMA16816(sacc[1], ah, bl0[2], bl0[3]);
                MMA16816(sacc[2], ah, bl1[0], bl1[1]);
                MMA16816(sacc[3], ah, bl1[2], bl1[3]);
            }

            if (sblk + ATT_BN - 1 > tw) {
                #pragma unroll
                for (int nf = 0; nf < 4; ++nf) {
                    int sg = sblk + nf * 8 + (lane & 3) * 2;
                    int tg0 = tw + r0, tg1 = tg0 + 8;
                    if (sg     > tg0) sacc[nf][0] = NEGA;
                    if (sg + 1 > tg0) sacc[nf][1] = NEGA;
                    if (sg     > tg1) sacc[nf][2] = NEGA;
                    if (sg + 1 > tg1) sacc[nf][3] = NEGA;
                }
            }

            float mx0 = NEGA, mx1 = NEGA;
            #pragma unroll
            for (int nf = 0; nf < 4; ++nf) {
                mx0 = fmaxf(mx0, fmaxf(sacc[nf][0], sacc[nf][1]));
                mx1 = fmaxf(mx1, fmaxf(sacc[nf][2], sacc[nf][3]));
            }
            mx0 = fmaxf(mx0, __shfl_xor_sync(0xffffffffu, mx0, 1));
            mx0 = fmaxf(mx0, __shfl_xor_sync(0xffffffffu, mx0, 2));
            mx1 = fmaxf(mx1, __shfl_xor_sync(0xffffffffu, mx1, 1));
            mx1 = fmaxf(mx1, __shfl_xor_sync(0xffffffffu, mx1, 2));
            float mn0 = fmaxf(mrow0, mx0), mn1 = fmaxf(mrow1, mx1);
            float al0 = __expf(mrow0 - mn0), al1 = __expf(mrow1 - mn1);
            float se0 = 0.f, se1 = 0.f;
            #pragma unroll
            for (int nf = 0; nf < 4; ++nf) {
                float p0 = __expf(sacc[nf][0] - mn0);
                float p1 = __expf(sacc[nf][1] - mn0);
                float p2 = __expf(sacc[nf][2] - mn1);
                float p3 = __expf(sacc[nf][3] - mn1);
                se0 += p0 + p1; se1 += p2 + p3;
                uint32_t pcol = (uint32_t)((nf * 8 + (lane & 3) * 2) * 2);
                uint32_t lo0, lo1;
                uint32_t hi0 = pack_split2(p0, p1, lo0);
                uint32_t hi1 = pack_split2(p2, p3, lo1);
                *(uint32_t*)(smem + (psh_base - s0u) + r0 * PROWB + pcol)       = hi0;
                *(uint32_t*)(smem + (psl_base - s0u) + r0 * PROWB + pcol)       = lo0;
                *(uint32_t*)(smem + (psh_base - s0u) + (r0 + 8) * PROWB + pcol) = hi1;
                *(uint32_t*)(smem + (psl_base - s0u) + (r0 + 8) * PROWB + pcol) = lo1;
            }
            se0 += __shfl_xor_sync(0xffffffffu, se0, 1);
            se0 += __shfl_xor_sync(0xffffffffu, se0, 2);
            se1 += __shfl_xor_sync(0xffffffffu, se1, 1);
            se1 += __shfl_xor_sync(0xffffffffu, se1, 2);
            mrow0 = mn0; mrow1 = mn1;
            lrow0 = lrow0 * al0 + se0;
            lrow1 = lrow1 * al1 + se1;
            #pragma unroll
            for (int a = 0; a < 16; ++a) {
                oacc[a][0] *= al0; oacc[a][1] *= al0;
                oacc[a][2] *= al1; oacc[a][3] *= al1;
            }
            __syncwarp();

            const uint32_t vrow = (uint32_t)((lane & 7) + ((lane >> 3) & 1) * 8);
            const uint32_t vco  = (uint32_t)((lane >> 4) * 16);
            #pragma unroll
            for (int ks2 = 0; ks2 < 2; ++ks2) {
                uint32_t ph[4], pl[4];
                uint32_t pa = (uint32_t)((lane & 15) * PROWB + (ks2 * 16 + (lane >> 4) * 8) * 2);
                LDSM4(ph, psh_base + pa);
                LDSM4(pl, psl_base + pa);
                #pragma unroll
                for (int hf = 0; hf < 8; ++hf) {
                    uint32_t bvh[4], bvl[4];
                    uint32_t voff = (ks2 * 16 + vrow) * KROWB + hf * 32 + vco;
                    LDSM4T(bvh, vH + voff);
                    LDSM4T(bvl, vL + voff);
                    MMA16816(oacc[2*hf],     ph, bvh[0], bvh[1]);
                    MMA16816(oacc[2*hf + 1], ph, bvh[2], bvh[3]);
                    MMA16816(oacc[2*hf],     pl, bvh[0], bvh[1]);
                    MMA16816(oacc[2*hf + 1], pl, bvh[2], bvh[3]);
                    MMA16816(oacc[2*hf],     ph, bvl[0], bvl[1]);
                    MMA16816(oacc[2*hf + 1], ph, bvl[2], bvl[3]);
                }
            }
        }
    }

    // epilogue: normalize + split-store enc as fp16 hi/lo
    float inv0 = 1.0f / lrow0, inv1 = 1.0f / lrow1;
    #pragma unroll
    for (int nt = 0; nt < 16; ++nt) {
        int hcol = nt * 8 + (lane & 3) * 2;
        size_t o0 = ((bT + tw + r0) * NC + n) * HC + hcol;
        size_t o1 = ((bT + tw + r0 + 8) * NC + n) * HC + hcol;
        uint32_t lo0, lo1;
        uint32_t hi0 = pack_split2_f16(oacc[nt][0] * inv0, oacc[nt][1] * inv0, lo0);
        uint32_t hi1 = pack_split2_f16(oacc[nt][2] * inv1, oacc[nt][3] * inv1, lo1);
        *(uint32_t*)((char*)ench + o0 * 2) = hi0;
        *(uint32_t*)((char*)encl + o0 * 2) = lo0;
        *(uint32_t*)((char*)ench + o1 * 2) = hi1;
        *(uint32_t*)((char*)encl + o1 * 2) = lo1;
    }
}

// ---------------- host ----------------
extern "C" void kernel_launch(void* const* d_in, const int* in_sizes, int n_in,
                              void* d_out, int out_size)
{
    (void)in_sizes; (void)n_in; (void)out_size;
    const float* x0  = (const float*)d_in[0];
    const float* x1  = (const float*)d_in[1];
    const int*   pos = (const int*)  d_in[2];
    const float* q0w = (const float*)d_in[4];
    const float* q1w = (const float*)d_in[5];
    const float* k0w = (const float*)d_in[6];
    const float* k1w = (const float*)d_in[7];
    const float* v0w = (const float*)d_in[8];
    const float* v1w = (const float*)d_in[9];
    const float* o0w = (const float*)d_in[10];
    const float* o1w = (const float*)d_in[11];
    const float* gt0 = (const float*)d_in[12];
    const float* gt1 = (const float*)d_in[13];
    const float* up0 = (const float*)d_in[14];
    const float* up1 = (const float*)d_in[15];
    const float* dw0 = (const float*)d_in[16];
    const float* dw1 = (const float*)d_in[17];
    const float* pa0 = (const float*)d_in[18];
    const float* pa1 = (const float*)d_in[19];
    const float* pf0 = (const float*)d_in[20];
    const float* pf1 = (const float*)d_in[21];
    float* out = (float*)d_out;

    float *qkv, *res, *gate;
    bf16 *qhb, *qlb, *khb, *klb, *vhb, *vlb;
    fp16 *preh, *prel, *ench, *encl, *hidh, *hidl, *guh, *gul, *wf;
    cudaGetSymbolAddress((void**)&qkv,  g_qkv);
    cudaGetSymbolAddress((void**)&res,  g_res);
    cudaGetSymbolAddress((void**)&gate, g_gate);
    cudaGetSymbolAddress((void**)&qhb,  g_qh);
    cudaGetSymbolAddress((void**)&qlb,  g_ql);
    cudaGetSymbolAddress((void**)&khb,  g_kh);
    cudaGetSymbolAddress((void**)&klb,  g_kl);
    cudaGetSymbolAddress((void**)&vhb,  g_vh);
    cudaGetSymbolAddress((void**)&vlb,  g_vl);
    cudaGetSymbolAddress((void**)&preh, g_preh);
    cudaGetSymbolAddress((void**)&prel, g_prel);
    cudaGetSymbolAddress((void**)&ench, g_ench);
    cudaGetSymbolAddress((void**)&encl, g_encl);
    cudaGetSymbolAddress((void**)&hidh, g_hidh);
    cudaGetSymbolAddress((void**)&hidl, g_hidl);
    cudaGetSymbolAddress((void**)&guh,  g_guh);
    cudaGetSymbolAddress((void**)&gul,  g_gul);
    cudaGetSymbolAddress((void**)&wf,   g_wf);

    cudaFuncSetAttribute(gemm_f16, cudaFuncAttributeMaxDynamicSharedMemorySize, TC_SMEM_F);
    cudaFuncSetAttribute(attn_mma_kernel, cudaFuncAttributeMaxDynamicSharedMemorySize, ATT_SMEM);

    const size_t QN   = (size_t)NHC * DC;     // 4194304
    const size_t KN   = (size_t)KHC * DC;     // 2097152
    const size_t FN   = (size_t)FC * DC;      // 16777216
    const size_t QKVN = QN + 2 * KN;          // 8388608
    // fp16 weight offsets in g_wf
    const size_t oqkv0 = 0, oqkv1 = QKVN;
    const size_t oo0 = 2 * QKVN,  oo1 = oo0 + QN;
    const size_t og0 = oo1 + QN,  og1 = og0 + FN;
    const size_t ou0 = og1 + FN,  ou1 = ou0 + FN;
    const size_t od0 = ou1 + FN,  od1 = od0 + FN;

    // [launch 0] all weight conversions -> fp16 single
    {
        CvtF16Jobs J;
        const float* srcs[NJOBS] = {q0w, k0w, v0w, q1w, k1w, v1w, o0w, o1w,
                                    gt0, gt1, up0, up1, dw0, dw1};
        const size_t offs[NJOBS] = {oqkv0, oqkv0 + QN, oqkv0 + QN + KN,
                                    oqkv1, oqkv1 + QN, oqkv1 + QN + KN,
                                    oo0, oo1, og0, og1, ou0, ou1, od0, od1};
        const size_t lens[NJOBS] = {QN, KN, KN, QN, KN, KN, QN, QN,
                                    FN, FN, FN, FN, FN, FN};
        int blk = 0;
        for (int j = 0; j < NJOBS; ++j) {
            J.src[j] = srcs[j];
            J.dst[j] = wf + offs[j];
            J.startblk[j] = blk;
            blk += (int)(lens[j] / 8192);
        }
        J.startblk[NJOBS] = blk;
        cvt_f16_kernel<<<blk, 256>>>(J);
    }

    // [launch 1] pre-attn rmsnorm -> fp16 hi/lo
    {
        dim3 g(BB * T0C, 2);
        rmsnorm2_f16_kernel<<<g, 256>>>(x0, x1, preh, prel, pa0, pa1, 0);
    }

    // [launches 2-3] QKV projection (Q half, KV half) — fp16x2 (profiled slot)
    {
        dim3 gq(2048 / GBN, T0C / GBM, 4);
        gemm_f16<<<gq, 512, TC_SMEM_F>>>(preh, prel, wf + oqkv0, wf + oqkv1,
                                         qkv, DC, 4096, 0, 0, 0, 0, 0, 0, 0, 0);
        gemm_f16<<<gq, 512, TC_SMEM_F>>>(preh, prel, wf + oqkv0 + QN, wf + oqkv1 + QN,
                                         qkv + 2048, DC, 4096, 0, 0, 0, 0, 0, 0, 0, 0);
    }

    // [launch 4] RoPE + scale + split -> bf16 hi/lo
    rope_split_kernel<<<BB * TOTC, 256>>>(qkv, pos, qhb, qlb, khb, klb, vhb, vlb);

    // [launch 5] attention -> fp16 ench/encl
    {
        dim3 ga(TOTC / ATT_BM, NC, BB);
        attn_mma_kernel<<<ga, 256, ATT_SMEM>>>(qhb, qlb, khb, klb, vhb, vlb, ench, encl);
    }

    // [launch 6] O projection + residual (per-stream x) — fp16x2
    {
        dim3 go(DC / GBN, T0C / GBM, 4);
        gemm_f16<<<go, 512, TC_SMEM_F>>>(ench, encl, wf + oo0, wf + oo1,
                                         res, NHC, DC, 2, x0, x1, 0, 0, 0, 0, 0);
    }

    // [launch 7] pre-ffw rmsnorm -> fp16 hi/lo (concat src)
    {
        dim3 g(BB * T0C, 2);
        rmsnorm2_f16_kernel<<<g, 256>>>(res, res, hidh, hidl, pf0, pf1, 1);
    }

    // [launches 8-9] gate (gelu) then up (fused gelu(gate)*up -> fp16 split)
    {
        dim3 gf(FC / GBN, T0C / GBM, 4);
        gemm_f16<<<gf, 512, TC_SMEM_F>>>(hidh, hidl, wf + og0, wf + og1,
                                         gate, DC, FC, 1, 0, 0, 0, 0, 0, 0, 0);
        gemm_f16<<<gf, 512, TC_SMEM_F>>>(hidh, hidl, wf + ou0, wf + ou1,
                                         gate, DC, FC, 3, 0, 0, 0, 0, gate, guh, gul);
    }

    // [launch 10] down projection + residual (concat res) -> out (stream-major)
    {
        dim3 gd(DC / GBN, T0C / GBM, 4);
        gemm_f16<<<gd, 512, TC_SMEM_F>>>(guh, gul, wf + od0, wf + od1,
                                         out, FC, DC, 2, res, 0, 1, 1, 0, 0, 0);
    }
}

// round 14
// speedup vs baseline: 2.3480x; 1.7124x over previous
#include <cuda_runtime.h>
#include <cuda_fp16.h>
#include <math.h>
#include <float.h>
#include <stdint.h>

// ---------------- problem constants ----------------
#define BB   2
#define T0C  1024
#define TOTC 2048
#define DC   2048
#define NC   16
#define KC   8
#define HC   128
#define FC   8192
#define NHC  2048   // N*H
#define KHC  1024   // K*H
#define GC   2      // N/K

typedef __half fp16;

// ---------------- helpers ----------------
__device__ __forceinline__ uint32_t smem_to_u32(const void* p) {
    uint32_t a;
    asm("{ .reg .u64 t; cvta.to.shared.u64 t, %1; cvt.u32.u64 %0, t; }" : "=r"(a) : "l"(p));
    return a;
}
#define LDSM4(r, addr) \
    asm volatile("ldmatrix.sync.aligned.m8n8.x4.shared.b16 {%0,%1,%2,%3}, [%4];" \
        : "=r"((r)[0]), "=r"((r)[1]), "=r"((r)[2]), "=r"((r)[3]) : "r"(addr))
#define LDSM4T(r, addr) \
    asm volatile("ldmatrix.sync.aligned.m8n8.x4.trans.shared.b16 {%0,%1,%2,%3}, [%4];" \
        : "=r"((r)[0]), "=r"((r)[1]), "=r"((r)[2]), "=r"((r)[3]) : "r"(addr))
#define MMAF16(d, a, b0, b1) \
    asm volatile("mma.sync.aligned.m16n8k16.row.col.f32.f16.f16.f32 " \
        "{%0,%1,%2,%3},{%4,%5,%6,%7},{%8,%9},{%0,%1,%2,%3};" \
        : "+f"((d)[0]), "+f"((d)[1]), "+f"((d)[2]), "+f"((d)[3]) \
        : "r"((a)[0]), "r"((a)[1]), "r"((a)[2]), "r"((a)[3]), "r"(b0), "r"(b1))
#define CP_ASYNC16(saddr, gaddr) \
    asm volatile("cp.async.cg.shared.global [%0], [%1], 16;" :: "r"(saddr), "l"(gaddr))
#define CP_COMMIT() asm volatile("cp.async.commit_group;" ::: "memory")
#define CP_WAIT(n)  asm volatile("cp.async.wait_group %0;" :: "n"(n) : "memory")

// ---------------- scratch (device globals; no runtime alloc) ----------------
__device__ float g_qkv [(size_t)BB*TOTC*4096];   // packed q(2048)|k(1024)|v(1024) fp32
__device__ float g_res [(size_t)BB*TOTC*DC];
__device__ float g_gate[(size_t)BB*TOTC*FC];

__device__ fp16 g_q   [(size_t)BB*TOTC*NHC];
__device__ fp16 g_k   [(size_t)BB*TOTC*KHC];
__device__ fp16 g_v   [(size_t)BB*TOTC*KHC];
__device__ fp16 g_pre [(size_t)BB*TOTC*DC];
__device__ fp16 g_enc [(size_t)BB*TOTC*NHC];
__device__ fp16 g_hid [(size_t)BB*TOTC*DC];
__device__ fp16 g_gu  [(size_t)BB*TOTC*FC];
__device__ fp16 g_wf  [125829120];  // fp16 weights: qkv0|qkv1|o0|o1|g0|g1|u0|u1|d0|d1

// ---------------- elementwise helpers ----------------
__device__ __forceinline__ float gelu_tanh(float x) {
    float x3 = x * x * x;
    return 0.5f * x * (1.0f + tanhf(0.7978845608028654f * (x + 0.044715f * x3)));
}
__device__ __forceinline__ uint32_t pack2h(float a, float b) {
    __half2 h = __floats2half2_rn(a, b);
    return *(uint32_t*)&h;
}

// ---------------- weight conversion: fp16 single, 14 jobs ----------------
#define NJOBS 14
struct CvtF16Jobs {
    const float* src[NJOBS];
    fp16* dst[NJOBS];
    int startblk[NJOBS + 1];
};

// 256 threads x 32 elems = 8192 elems/block
__global__ void cvt_f16_kernel(CvtF16Jobs J)
{
    int bid = blockIdx.x;
    int j = 0;
    #pragma unroll
    for (int t = 1; t < NJOBS; ++t) if (bid >= J.startblk[t]) j = t;
    int blk_off = (bid - J.startblk[j]) * 8192;
    const float* src = J.src[j];
    fp16* dst = J.dst[j];

    float4 va[4][2];
    int idx[4];
    #pragma unroll
    for (int u = 0; u < 4; ++u) {
        idx[u] = blk_off + (u * 256 + threadIdx.x) * 8;
        va[u][0] = *(const float4*)(src + idx[u]);
        va[u][1] = *(const float4*)(src + idx[u] + 4);
    }
    #pragma unroll
    for (int u = 0; u < 4; ++u) {
        uint4 o;
        o.x = pack2h(va[u][0].x, va[u][0].y);
        o.y = pack2h(va[u][0].z, va[u][0].w);
        o.z = pack2h(va[u][1].x, va[u][1].y);
        o.w = pack2h(va[u][1].z, va[u][1].w);
        *(uint4*)(dst + idx[u]) = o;
    }
}

// ---------------- rmsnorm pair -> fp16 single ----------------
// srcmode 0: src per-stream (s0/s1, rows b*T0+t); srcmode 1: concat src s0
__global__ void rmsnorm2_f16_kernel(const float* __restrict__ s0, const float* __restrict__ s1,
                                    fp16* __restrict__ dst,
                                    const float* __restrict__ sc0, const float* __restrict__ sc1,
                                    int srcmode)
{
    int istream = blockIdx.y;
    int row = blockIdx.x;
    int b = row / T0C, t = row % T0C;
    size_t crow = (size_t)b * TOTC + (size_t)istream * T0C + t;
    const float* base = istream ? s1 : s0;
    const float* scale = istream ? sc1 : sc0;
    const float* s = srcmode ? (s0 + crow * DC) : (base + (size_t)row * DC);
    fp16* o = dst + crow * DC;

    __shared__ float red[256];
    float ss = 0.f;
    for (int d = threadIdx.x; d < DC; d += 256) { float v = s[d]; ss += v * v; }
    red[threadIdx.x] = ss;
    __syncthreads();
    for (int st = 128; st > 0; st >>= 1) {
        if (threadIdx.x < st) red[threadIdx.x] += red[threadIdx.x + st];
        __syncthreads();
    }
    float inv = rsqrtf(red[0] * (1.0f / DC) + 1e-6f);
    for (int d = threadIdx.x; d < DC; d += 256) {
        float v = s[d] * inv * (1.0f + scale[d]);
        o[d] = __float2half_rn(v);
    }
}

// ---------------- rope + convert (fp32 qkv -> fp16 q,k,v) ----------------
__global__ void rope_split_kernel(const float* __restrict__ qkv, const int* __restrict__ positions,
                                  fp16* __restrict__ q, fp16* __restrict__ k, fp16* __restrict__ v)
{
    int row = blockIdx.x;
    float pos = (float)positions[row];
    const float QSCALE = 0.08838834764831845f;
    const float* src = qkv + (size_t)row * 4096;

    __shared__ float ssn[64], scs[64];
    if (threadIdx.x < 64) {
        int j = threadIdx.x;
        float ts = powf(10000.0f, (float)j * (1.0f / 64.0f));
        float sn, cs;
        sincosf(pos / ts, &sn, &cs);
        ssn[j] = sn; scs[j] = cs;
    }
    __syncthreads();

    for (int w = threadIdx.x; w < (NC + KC) * 64; w += 256) {
        int head = w >> 6;
        int j = w & 63;
        float sn = ssn[j], cs = scs[j];
        if (head < NC) {
            float x1 = src[head * HC + j], x2 = src[head * HC + j + 64];
            size_t o = ((size_t)row * NC + head) * HC;
            q[o + j]      = __float2half_rn((x1 * cs - x2 * sn) * QSCALE);
            q[o + j + 64] = __float2half_rn((x2 * cs + x1 * sn) * QSCALE);
        } else {
            int kkh = head - NC;
            float x1 = src[2048 + kkh * HC + j], x2 = src[2048 + kkh * HC + j + 64];
            size_t o = ((size_t)row * KC + kkh) * HC;
            k[o + j]      = __float2half_rn(x1 * cs - x2 * sn);
            k[o + j + 64] = __float2half_rn(x2 * cs + x1 * sn);
        }
    }
    for (int idx = threadIdx.x; idx < KHC; idx += 256) {
        size_t o = (size_t)row * KHC + idx;
        v[o] = __float2half_rn(src[3072 + idx]);
    }
}

// ---------------- GEMM geometry ----------------
#define GBM 256
#define GBN 128
#define GBK 32
#define GSTAGES 5
#define ROWB   80
#define TILEA_B (256 * ROWB)                 // 20480
#define TILEW_B (128 * ROWB)                 // 10240
#define STAGE_F (TILEA_B + TILEW_B)          // 30720 (fp16 single)
#define TC_SMEM_F (GSTAGES * STAGE_F)        // 153600

// ---------------- fp16 single-pass GEMM (all projections) ----------------
// A single fp16, W single fp16 per stream (W0/W1 selected by stream i).
// epi: 0 plain, 1 gelu, 2 +residual, 3 gate-mul->GU fp16
// resmode: 0 per-stream R (R0/R1 + b*T0*ldC), 1 concat R0 (+ arow0*ldC)
// outmode: 0 concat rows, 1 stream-major rows
__global__ __launch_bounds__(512, 1)
void gemm_f16(const fp16* __restrict__ A_,
              const fp16* __restrict__ W0, const fp16* __restrict__ W1,
              float* __restrict__ C_, int Kd, int ldC, int epi,
              const float* __restrict__ R0, const float* __restrict__ R1,
              int resmode, int outmode,
              const float* __restrict__ G_, fp16* __restrict__ GU_)
{
    extern __shared__ char smem[];
    const uint32_t s0 = smem_to_u32(smem);

    const int tid = threadIdx.x;
    const int lane = tid & 31, warp = tid >> 5;
    const int wm = warp >> 2, wn = warp & 3;      // warp tile 64(m) x 32(n)

    const int z = blockIdx.z, i = z >> 1, b = z & 1;
    const size_t arow0 = (size_t)b * TOTC + (size_t)i * T0C;
    const fp16* A = A_ + arow0 * Kd;
    const fp16* W = i ? W1 : W0;
    float* C = (outmode == 0) ? (C_ + arow0 * (size_t)ldC)
                              : (C_ + ((size_t)i * BB * T0C + (size_t)b * T0C) * (size_t)ldC);
    const float* R = 0;
    if (epi == 2) R = (resmode == 0) ? ((i ? R1 : R0) + (size_t)b * T0C * ldC)
                                     : (R0 + arow0 * (size_t)ldC);
    const float* G = 0; fp16* GU = 0;
    if (epi == 3) { G = G_ + arow0 * (size_t)ldC; GU = GU_ + arow0 * (size_t)ldC; }

    const int m0 = blockIdx.y * GBM, n0 = blockIdx.x * GBN;
    const int nk = Kd / GBK;

    // 1536 16B chunks per stage: A 1024, W 512. 3 per thread.
    #define ISSUE_STAGE_F(cc) do {                                               \
        int kk0 = (cc) * GBK;                                                    \
        uint32_t sbase = s0 + ((cc) % GSTAGES) * STAGE_F;                        \
        _Pragma("unroll")                                                        \
        for (int it = 0; it < 3; ++it) {                                         \
            int idx = tid + it * 512;                                            \
            const fp16* gp; uint32_t sa;                                         \
            if (idx < 1024) {                                                    \
                int row = idx >> 2, ch = idx & 3;                                \
                sa = sbase + row * ROWB + ch * 16;                               \
                gp = A + (size_t)(m0 + row) * Kd + kk0 + ch * 8;                 \
            } else {                                                             \
                int cid = idx - 1024;                                            \
                int row = cid >> 2, ch = cid & 3;                                \
                sa = sbase + TILEA_B + row * ROWB + ch * 16;                     \
                gp = W + (size_t)(n0 + row) * Kd + kk0 + ch * 8;                 \
            }                                                                    \
            CP_ASYNC16(sa, gp);                                                  \
        }                                                                        \
        CP_COMMIT();                                                             \
    } while (0)

    float acc[4][4][4];
    #pragma unroll
    for (int mf = 0; mf < 4; ++mf)
        #pragma unroll
        for (int nf = 0; nf < 4; ++nf)
            #pragma unroll
            for (int r = 0; r < 4; ++r) acc[mf][nf][r] = 0.f;

    const int a_row = wm * 64 + (lane & 15);
    const int a_cj  = lane >> 4;
    const int b_row = wn * 32 + (lane & 7) + ((lane >> 4) & 1) * 8;
    const int b_cj  = (lane >> 3) & 1;

    ISSUE_STAGE_F(0);
    ISSUE_STAGE_F(1);
    ISSUE_STAGE_F(2);
    ISSUE_STAGE_F(3);

    for (int c = 0; c < nk; ++c) {
        if (c + 3 < nk) CP_WAIT(3); else CP_WAIT(0);
        __syncthreads();

        uint32_t sbase = s0 + (c % GSTAGES) * STAGE_F;
        uint32_t aB = sbase, bB = sbase + TILEA_B;

        #pragma unroll
        for (int ks = 0; ks < 2; ++ks) {
            uint32_t aoff = (uint32_t)(a_row * ROWB + (ks * 2 + a_cj) * 16);
            uint32_t boff = (uint32_t)(b_row * ROWB + (ks * 2 + b_cj) * 16);

            uint32_t ah[4][4], bh[2][4];
            #pragma unroll
            for (int mf = 0; mf < 4; ++mf) LDSM4(ah[mf], aB + aoff + mf * (16 * ROWB));
            #pragma unroll
            for (int nf2 = 0; nf2 < 2; ++nf2) LDSM4(bh[nf2], bB + boff + nf2 * (16 * ROWB));

            #pragma unroll
            for (int nf2 = 0; nf2 < 2; ++nf2)
                #pragma unroll
                for (int mf = 0; mf < 4; ++mf) {
                    MMAF16(acc[mf][nf2 * 2],     ah[mf], bh[nf2][0], bh[nf2][1]);
                    MMAF16(acc[mf][nf2 * 2 + 1], ah[mf], bh[nf2][2], bh[nf2][3]);
                }

            if (ks == 0 && c + 4 < nk) ISSUE_STAGE_F(c + 4);
        }
    }

    #pragma unroll
    for (int mf = 0; mf < 4; ++mf) {
        int r0 = m0 + wm * 64 + mf * 16 + (lane >> 2);
        #pragma unroll
        for (int nf = 0; nf < 4; ++nf) {
            int col = n0 + wn * 32 + nf * 8 + (lane & 3) * 2;
            float2 v0 = make_float2(acc[mf][nf][0], acc[mf][nf][1]);
            float2 v1 = make_float2(acc[mf][nf][2], acc[mf][nf][3]);
            if (epi == 3) {
                float2 g0 = *(const float2*)(G + (size_t)r0 * ldC + col);
                float2 g1 = *(const float2*)(G + (size_t)(r0 + 8) * ldC + col);
                *(uint32_t*)((char*)GU + ((size_t)r0 * ldC + col) * 2)       = pack2h(v0.x * g0.x, v0.y * g0.y);
                *(uint32_t*)((char*)GU + ((size_t)(r0 + 8) * ldC + col) * 2) = pack2h(v1.x * g1.x, v1.y * g1.y);
            } else {
                if (epi == 1) {
                    v0.x = gelu_tanh(v0.x); v0.y = gelu_tanh(v0.y);
                    v1.x = gelu_tanh(v1.x); v1.y = gelu_tanh(v1.y);
                } else if (epi == 2) {
                    float2 ra = *(const float2*)(R + (size_t)r0 * ldC + col);
                    float2 rb = *(const float2*)(R + (size_t)(r0 + 8) * ldC + col);
                    v0.x += ra.x; v0.y += ra.y;
                    v1.x += rb.x; v1.y += rb.y;
                }
                *(float2*)(C + (size_t)r0 * ldC + col)       = v0;
                *(float2*)(C + (size_t)(r0 + 8) * ldC + col) = v1;
            }
        }
    }
}

// ---------------- attention: single-fp16 flash kernel ----------------
#define ATT_BM 128
#define ATT_BN 32
#define QROWB 272
#define KROWB 272
#define PROWB 80
#define SQ 0
#define SKV 34816
#define KVTILE 8704
#define SP 69632
#define ATT_SMEM 79872
#define NEGA (-1e30f)

__global__ __launch_bounds__(256, 1)
void attn_mma_kernel(const fp16* __restrict__ q, const fp16* __restrict__ k,
                     const fp16* __restrict__ v, fp16* __restrict__ enc)
{
    extern __shared__ char smem[];
    const uint32_t s0u = smem_to_u32(smem);
    const int tid = threadIdx.x, lane = tid & 31, w = tid >> 5;
    const int bq = blockIdx.z;
    const int n = blockIdx.y;
    const int kk = n >> 1;
    const int t0 = ((int)gridDim.x - 1 - (int)blockIdx.x) * ATT_BM;
    const size_t bT = (size_t)bq * TOTC;

    // Q tile: 128 rows x 128 fp16 = 2048 16B chunks
    #pragma unroll
    for (int it = 0; it < 8; ++it) {
        int idx = tid + it * 256;
        int row = idx >> 4, ch = idx & 15;
        const fp16* src = q + ((bT + t0 + row) * NC + n) * HC + ch * 8;
        CP_ASYNC16(s0u + SQ + row * QROWB + ch * 16, src);
    }
    CP_COMMIT();

    #define LOAD_KV(j) do {                                                        \
        int _bf = (j) & 1; int _s0 = (j) * ATT_BN;                                 \
        _Pragma("unroll")                                                          \
        for (int it = 0; it < 4; ++it) {                                           \
            int idx = tid + it * 256;                                              \
            int tt = idx >> 9, cid = idx & 511, row = cid >> 4, ch = cid & 15;     \
            const fp16* srcp = (tt ? v : k) + ((bT + _s0 + row) * KC + kk) * HC + ch * 8; \
            CP_ASYNC16(s0u + SKV + (_bf * 2 + tt) * KVTILE + row * KROWB + ch * 16, srcp); \
        }                                                                          \
        CP_COMMIT();                                                               \
    } while (0)

    const int nb = t0 / ATT_BN + 4;
    LOAD_KV(0);

    const int tw = t0 + w * 16;
    const int r0 = lane >> 2;
    float oacc[16][4];
    #pragma unroll
    for (int a = 0; a < 16; ++a) { oacc[a][0] = oacc[a][1] = oacc[a][2] = oacc[a][3] = 0.f; }
    float mrow0 = NEGA, mrow1 = NEGA, lrow0 = 0.f, lrow1 = 0.f;

    const uint32_t ps_base = s0u + SP + (w * 16) * PROWB;

    for (int j = 0; j < nb; ++j) {
        CP_WAIT(0);
        __syncthreads();
        if (j + 1 < nb) LOAD_KV(j + 1);

        const int sblk = j * ATT_BN;
        const int bf = j & 1;
        const uint32_t kB = s0u + SKV + (bf * 2 + 0) * KVTILE;
        const uint32_t vB = s0u + SKV + (bf * 2 + 1) * KVTILE;

        if (sblk <= tw + 15) {
            // ---- S = Q K^T (fp16 single) ----
            float sacc[4][4];
            #pragma unroll
            for (int nf = 0; nf < 4; ++nf) { sacc[nf][0]=sacc[nf][1]=sacc[nf][2]=sacc[nf][3]=0.f; }
            const uint32_t aoff_base = (uint32_t)((w * 16 + (lane & 15)) * QROWB + (lane >> 4) * 16);
            const uint32_t brow = (uint32_t)((lane & 7) + ((lane >> 4) & 1) * 8);
            const uint32_t bco  = (uint32_t)(((lane >> 3) & 1) * 16);
            #pragma unroll
            for (int ks = 0; ks < 8; ++ks) {
                uint32_t ah[4], bh0[4], bh1[4];
                uint32_t aoff = aoff_base + ks * 32;
                LDSM4(ah, s0u + SQ + aoff);
                uint32_t boff0 = brow * KROWB + ks * 32 + bco;
                uint32_t boff1 = boff0 + 16 * KROWB;
                LDSM4(bh0, kB + boff0); LDSM4(bh1, kB + boff1);
                MMAF16(sacc[0], ah, bh0[0], bh0[1]);
                MMAF16(sacc[1], ah, bh0[2], bh0[3]);
                MMAF16(sacc[2], ah, bh1[0], bh1[1]);
                MMAF16(sacc[3], ah, bh1[2], bh1[3]);
            }

            // ---- causal mask (diagonal blocks only) ----
            if (sblk + ATT_BN - 1 > tw) {
                #pragma unroll
                for (int nf = 0; nf < 4; ++nf) {
                    int sg = sblk + nf * 8 + (lane & 3) * 2;
                    int tg0 = tw + r0, tg1 = tg0 + 8;
                    if (sg     > tg0) sacc[nf][0] = NEGA;
                    if (sg + 1 > tg0) sacc[nf][1] = NEGA;
                    if (sg     > tg1) sacc[nf][2] = NEGA;
                    if (sg + 1 > tg1) sacc[nf][3] = NEGA;
                }
            }

            // ---- online softmax ----
            float mx0 = NEGA, mx1 = NEGA;
            #pragma unroll
            for (int nf = 0; nf < 4; ++nf) {
                mx0 = fmaxf(mx0, fmaxf(sacc[nf][0], sacc[nf][1]));
                mx1 = fmaxf(mx1, fmaxf(sacc[nf][2], sacc[nf][3]));
            }
            mx0 = fmaxf(mx0, __shfl_xor_sync(0xffffffffu, mx0, 1));
            mx0 = fmaxf(mx0, __shfl_xor_sync(0xffffffffu, mx0, 2));
            mx1 = fmaxf(mx1, __shfl_xor_sync(0xffffffffu, mx1, 1));
            mx1 = fmaxf(mx1, __shfl_xor_sync(0xffffffffu, mx1, 2));
            float mn0 = fmaxf(mrow0, mx0), mn1 = fmaxf(mrow1, mx1);
            float al0 = __expf(mrow0 - mn0), al1 = __expf(mrow1 - mn1);
            float se0 = 0.f, se1 = 0.f;
            #pragma unroll
            for (int nf = 0; nf < 4; ++nf) {
                float p0 = __expf(sacc[nf][0] - mn0);
                float p1 = __expf(sacc[nf][1] - mn0);
                float p2 = __expf(sacc[nf][2] - mn1);
                float p3 = __expf(sacc[nf][3] - mn1);
                se0 += p0 + p1; se1 += p2 + p3;
                uint32_t pcol = (uint32_t)((nf * 8 + (lane & 3) * 2) * 2);
                *(uint32_t*)(smem + (ps_base - s0u) + r0 * PROWB + pcol)       = pack2h(p0, p1);
                *(uint32_t*)(smem + (ps_base - s0u) + (r0 + 8) * PROWB + pcol) = pack2h(p2, p3);
            }
            se0 += __shfl_xor_sync(0xffffffffu, se0, 1);
            se0 += __shfl_xor_sync(0xffffffffu, se0, 2);
            se1 += __shfl_xor_sync(0xffffffffu, se1, 1);
            se1 += __shfl_xor_sync(0xffffffffu, se1, 2);
            mrow0 = mn0; mrow1 = mn1;
            lrow0 = lrow0 * al0 + se0;
            lrow1 = lrow1 * al1 + se1;
            #pragma unroll
            for (int a = 0; a < 16; ++a) {
                oacc[a][0] *= al0; oacc[a][1] *= al0;
                oacc[a][2] *= al1; oacc[a][3] *= al1;
            }
            __syncwarp();

            // ---- O += P V (fp16 single) ----
            const uint32_t vrow = (uint32_t)((lane & 7) + ((lane >> 3) & 1) * 8);
            const uint32_t vco  = (uint32_t)((lane >> 4) * 16);
            #pragma unroll
            for (int ks2 = 0; ks2 < 2; ++ks2) {
                uint32_t ph[4];
                uint32_t pa = (uint32_t)((lane & 15) * PROWB + (ks2 * 16 + (lane >> 4) * 8) * 2);
                LDSM4(ph, ps_base + pa);
                #pragma unroll
                for (int hf = 0; hf < 8; ++hf) {
                    uint32_t bvh[4];
                    uint32_t voff = (ks2 * 16 + vrow) * KROWB + hf * 32 + vco;
                    LDSM4T(bvh, vB + voff);
                    MMAF16(oacc[2*hf],     ph, bvh[0], bvh[1]);
                    MMAF16(oacc[2*hf + 1], ph, bvh[2], bvh[3]);
                }
            }
        }
    }

    // epilogue: normalize + store enc fp16
    float inv0 = 1.0f / lrow0, inv1 = 1.0f / lrow1;
    #pragma unroll
    for (int nt = 0; nt < 16; ++nt) {
        int hcol = nt * 8 + (lane & 3) * 2;
        size_t o0 = ((bT + tw + r0) * NC + n) * HC + hcol;
        size_t o1 = ((bT + tw + r0 + 8) * NC + n) * HC + hcol;
        *(uint32_t*)((char*)enc + o0 * 2) = pack2h(oacc[nt][0] * inv0, oacc[nt][1] * inv0);
        *(uint32_t*)((char*)enc + o1 * 2) = pack2h(oacc[nt][2] * inv1, oacc[nt][3] * inv1);
    }
}

// ---------------- host ----------------
extern "C" void kernel_launch(void* const* d_in, const int* in_sizes, int n_in,
                              void* d_out, int out_size)
{
    (void)in_sizes; (void)n_in; (void)out_size;
    const float* x0  = (const float*)d_in[0];
    const float* x1  = (const float*)d_in[1];
    const int*   pos = (const int*)  d_in[2];
    const float* q0w = (const float*)d_in[4];
    const float* q1w = (const float*)d_in[5];
    const float* k0w = (const float*)d_in[6];
    const float* k1w = (const float*)d_in[7];
    const float* v0w = (const float*)d_in[8];
    const float* v1w = (const float*)d_in[9];
    const float* o0w = (const float*)d_in[10];
    const float* o1w = (const float*)d_in[11];
    const float* gt0 = (const float*)d_in[12];
    const float* gt1 = (const float*)d_in[13];
    const float* up0 = (const float*)d_in[14];
    const float* up1 = (const float*)d_in[15];
    const float* dw0 = (const float*)d_in[16];
    const float* dw1 = (const float*)d_in[17];
    const float* pa0 = (const float*)d_in[18];
    const float* pa1 = (const float*)d_in[19];
    const float* pf0 = (const float*)d_in[20];
    const float* pf1 = (const float*)d_in[21];
    float* out = (float*)d_out;

    float *qkv, *res, *gate;
    fp16 *qb, *kb, *vb, *pre, *enc, *hid, *gu, *wf;
    cudaGetSymbolAddress((void**)&qkv,  g_qkv);
    cudaGetSymbolAddress((void**)&res,  g_res);
    cudaGetSymbolAddress((void**)&gate, g_gate);
    cudaGetSymbolAddress((void**)&qb,   g_q);
    cudaGetSymbolAddress((void**)&kb,   g_k);
    cudaGetSymbolAddress((void**)&vb,   g_v);
    cudaGetSymbolAddress((void**)&pre,  g_pre);
    cudaGetSymbolAddress((void**)&enc,  g_enc);
    cudaGetSymbolAddress((void**)&hid,  g_hid);
    cudaGetSymbolAddress((void**)&gu,   g_gu);
    cudaGetSymbolAddress((void**)&wf,   g_wf);

    cudaFuncSetAttribute(gemm_f16, cudaFuncAttributeMaxDynamicSharedMemorySize, TC_SMEM_F);
    cudaFuncSetAttribute(attn_mma_kernel, cudaFuncAttributeMaxDynamicSharedMemorySize, ATT_SMEM);

    const size_t QN   = (size_t)NHC * DC;     // 4194304
    const size_t KN   = (size_t)KHC * DC;     // 2097152
    const size_t FN   = (size_t)FC * DC;      // 16777216
    const size_t QKVN = QN + 2 * KN;          // 8388608
    const size_t oqkv0 = 0, oqkv1 = QKVN;
    const size_t oo0 = 2 * QKVN,  oo1 = oo0 + QN;
    const size_t og0 = oo1 + QN,  og1 = og0 + FN;
    const size_t ou0 = og1 + FN,  ou1 = ou0 + FN;
    const size_t od0 = ou1 + FN,  od1 = od0 + FN;

    // [launch 0] all weight conversions -> fp16 single
    {
        CvtF16Jobs J;
        const float* srcs[NJOBS] = {q0w, k0w, v0w, q1w, k1w, v1w, o0w, o1w,
                                    gt0, gt1, up0, up1, dw0, dw1};
        const size_t offs[NJOBS] = {oqkv0, oqkv0 + QN, oqkv0 + QN + KN,
                                    oqkv1, oqkv1 + QN, oqkv1 + QN + KN,
                                    oo0, oo1, og0, og1, ou0, ou1, od0, od1};
        const size_t lens[NJOBS] = {QN, KN, KN, QN, KN, KN, QN, QN,
                                    FN, FN, FN, FN, FN, FN};
        int blk = 0;
        for (int j = 0; j < NJOBS; ++j) {
            J.src[j] = srcs[j];
            J.dst[j] = wf + offs[j];
            J.startblk[j] = blk;
            blk += (int)(lens[j] / 8192);
        }
        J.startblk[NJOBS] = blk;
        cvt_f16_kernel<<<blk, 256>>>(J);
    }

    // [launch 1] pre-attn rmsnorm -> fp16
    {
        dim3 g(BB * T0C, 2);
        rmsnorm2_f16_kernel<<<g, 256>>>(x0, x1, pre, pa0, pa1, 0);
    }

    // [launches 2-3] QKV projection (Q half, KV half) — fp16 single (profiled slot)
    {
        dim3 gq(2048 / GBN, T0C / GBM, 4);
        gemm_f16<<<gq, 512, TC_SMEM_F>>>(pre, wf + oqkv0, wf + oqkv1,
                                         qkv, DC, 4096, 0, 0, 0, 0, 0, 0, 0);
        gemm_f16<<<gq, 512, TC_SMEM_F>>>(pre, wf + oqkv0 + QN, wf + oqkv1 + QN,
                                         qkv + 2048, DC, 4096, 0, 0, 0, 0, 0, 0, 0);
    }

    // [launch 4] RoPE + scale -> fp16 q,k,v
    rope_split_kernel<<<BB * TOTC, 256>>>(qkv, pos, qb, kb, vb);

    // [launch 5] attention -> fp16 enc
    {
        dim3 ga(TOTC / ATT_BM, NC, BB);
        attn_mma_kernel<<<ga, 256, ATT_SMEM>>>(qb, kb, vb, enc);
    }

    // [launch 6] O projection + residual (per-stream x)
    {
        dim3 go(DC / GBN, T0C / GBM, 4);
        gemm_f16<<<go, 512, TC_SMEM_F>>>(enc, wf + oo0, wf + oo1,
                                         res, NHC, DC, 2, x0, x1, 0, 0, 0, 0);
    }

    // [launch 7] pre-ffw rmsnorm -> fp16 (concat src)
    {
        dim3 g(BB * T0C, 2);
        rmsnorm2_f16_kernel<<<g, 256>>>(res, res, hid, pf0, pf1, 1);
    }

    // [launches 8-9] gate (gelu) then up (fused gelu(gate)*up -> fp16)
    {
        dim3 gf(FC / GBN, T0C / GBM, 4);
        gemm_f16<<<gf, 512, TC_SMEM_F>>>(hid, wf + og0, wf + og1,
                                         gate, DC, FC, 1, 0, 0, 0, 0, 0, 0);
        gemm_f16<<<gf, 512, TC_SMEM_F>>>(hid, wf + ou0, wf + ou1,
                                         gate, DC, FC, 3, 0, 0, 0, 0, gate, gu);
    }

    // [launch 10] down projection + residual (concat res) -> out (stream-major)
    {
        dim3 gd(DC / GBN, T0C / GBM, 4);
        gemm_f16<<<gd, 512, TC_SMEM_F>>>(gu, wf + od0, wf + od1,
                                         out, FC, DC, 2, res, 0, 1, 1, 0, 0);
    }
}

// round 15
// speedup vs baseline: 2.3746x; 1.0113x over previous
#include <cuda_runtime.h>
#include <cuda_fp16.h>
#include <math.h>
#include <float.h>
#include <stdint.h>

// ---------------- problem constants ----------------
#define BB   2
#define T0C  1024
#define TOTC 2048
#define DC   2048
#define NC   16
#define KC   8
#define HC   128
#define FC   8192
#define NHC  2048   // N*H
#define KHC  1024   // K*H
#define GC   2      // N/K

typedef __half fp16;

// ---------------- helpers ----------------
__device__ __forceinline__ uint32_t smem_to_u32(const void* p) {
    uint32_t a;
    asm("{ .reg .u64 t; cvta.to.shared.u64 t, %1; cvt.u32.u64 %0, t; }" : "=r"(a) : "l"(p));
    return a;
}
#define LDSM4(r, addr) \
    asm volatile("ldmatrix.sync.aligned.m8n8.x4.shared.b16 {%0,%1,%2,%3}, [%4];" \
        : "=r"((r)[0]), "=r"((r)[1]), "=r"((r)[2]), "=r"((r)[3]) : "r"(addr))
#define LDSM4T(r, addr) \
    asm volatile("ldmatrix.sync.aligned.m8n8.x4.trans.shared.b16 {%0,%1,%2,%3}, [%4];" \
        : "=r"((r)[0]), "=r"((r)[1]), "=r"((r)[2]), "=r"((r)[3]) : "r"(addr))
#define MMAF16(d, a, b0, b1) \
    asm volatile("mma.sync.aligned.m16n8k16.row.col.f32.f16.f16.f32 " \
        "{%0,%1,%2,%3},{%4,%5,%6,%7},{%8,%9},{%0,%1,%2,%3};" \
        : "+f"((d)[0]), "+f"((d)[1]), "+f"((d)[2]), "+f"((d)[3]) \
        : "r"((a)[0]), "r"((a)[1]), "r"((a)[2]), "r"((a)[3]), "r"(b0), "r"(b1))
#define CP_ASYNC16(saddr, gaddr) \
    asm volatile("cp.async.cg.shared.global [%0], [%1], 16;" :: "r"(saddr), "l"(gaddr))
#define CP_COMMIT() asm volatile("cp.async.commit_group;" ::: "memory")
#define CP_WAIT(n)  asm volatile("cp.async.wait_group %0;" :: "n"(n) : "memory")

// ---------------- scratch (device globals; no runtime alloc) ----------------
__device__ float g_res [(size_t)BB*TOTC*DC];

__device__ fp16 g_qkvh[(size_t)BB*TOTC*4096];    // packed q|k|v fp16 (pre-rope)
__device__ fp16 g_q   [(size_t)BB*TOTC*NHC];
__device__ fp16 g_k   [(size_t)BB*TOTC*KHC];
__device__ fp16 g_v   [(size_t)BB*TOTC*KHC];
__device__ fp16 g_pre [(size_t)BB*TOTC*DC];
__device__ fp16 g_enc [(size_t)BB*TOTC*NHC];
__device__ fp16 g_hid [(size_t)BB*TOTC*DC];
__device__ fp16 g_gu  [(size_t)BB*TOTC*FC];
__device__ fp16 g_wf  [125829120];  // fp16 weights: qkv0|qkv1|o0|o1|gu0(ilv)|gu1(ilv)|d0|d1

// ---------------- elementwise helpers ----------------
__device__ __forceinline__ float gelu_tanh(float x) {
    float x3 = x * x * x;
    return 0.5f * x * (1.0f + tanhf(0.7978845608028654f * (x + 0.044715f * x3)));
}
__device__ __forceinline__ uint32_t pack2h(float a, float b) {
    __half2 h = __floats2half2_rn(a, b);
    return *(uint32_t*)&h;
}

// ---------------- weight conversion: fp16 single, 14 jobs, optional row-interleave ----------------
// ilv: 0 = straight copy; 1 = write row r to row 2r (even); 2 = row r to 2r+1 (odd).
// Interleaved jobs have K = 2048 columns.
#define NJOBS 14
struct CvtF16Jobs {
    const float* src[NJOBS];
    fp16* dst[NJOBS];
    int ilv[NJOBS];
    int startblk[NJOBS + 1];
};

// 256 threads x 32 elems = 8192 elems/block
__global__ void cvt_f16_kernel(CvtF16Jobs J)
{
    int bid = blockIdx.x;
    int j = 0;
    #pragma unroll
    for (int t = 1; t < NJOBS; ++t) if (bid >= J.startblk[t]) j = t;
    int blk_off = (bid - J.startblk[j]) * 8192;
    const float* src = J.src[j];
    fp16* dst = J.dst[j];
    int ilv = J.ilv[j];

    float4 va[4][2];
    int idx[4];
    #pragma unroll
    for (int u = 0; u < 4; ++u) {
        idx[u] = blk_off + (u * 256 + threadIdx.x) * 8;
        va[u][0] = *(const float4*)(src + idx[u]);
        va[u][1] = *(const float4*)(src + idx[u] + 4);
    }
    #pragma unroll
    for (int u = 0; u < 4; ++u) {
        uint4 o;
        o.x = pack2h(va[u][0].x, va[u][0].y);
        o.y = pack2h(va[u][0].z, va[u][0].w);
        o.z = pack2h(va[u][1].x, va[u][1].y);
        o.w = pack2h(va[u][1].z, va[u][1].w);
        int didx = idx[u];
        if (ilv) {
            int row = didx >> 11, col = didx & 2047;
            didx = (((row << 1) | (ilv - 1)) << 11) | col;
        }
        *(uint4*)(dst + didx) = o;
    }
}

// ---------------- rmsnorm pair -> fp16 single ----------------
// srcmode 0: src per-stream (s0/s1, rows b*T0+t); srcmode 1: concat src s0
__global__ void rmsnorm2_f16_kernel(const float* __restrict__ s0, const float* __restrict__ s1,
                                    fp16* __restrict__ dst,
                                    const float* __restrict__ sc0, const float* __restrict__ sc1,
                                    int srcmode)
{
    int istream = blockIdx.y;
    int row = blockIdx.x;
    int b = row / T0C, t = row % T0C;
    size_t crow = (size_t)b * TOTC + (size_t)istream * T0C + t;
    const float* base = istream ? s1 : s0;
    const float* scale = istream ? sc1 : sc0;
    const float* s = srcmode ? (s0 + crow * DC) : (base + (size_t)row * DC);
    fp16* o = dst + crow * DC;

    __shared__ float red[256];
    float ss = 0.f;
    for (int d = threadIdx.x; d < DC; d += 256) { float v = s[d]; ss += v * v; }
    red[threadIdx.x] = ss;
    __syncthreads();
    for (int st = 128; st > 0; st >>= 1) {
        if (threadIdx.x < st) red[threadIdx.x] += red[threadIdx.x + st];
        __syncthreads();
    }
    float inv = rsqrtf(red[0] * (1.0f / DC) + 1e-6f);
    for (int d = threadIdx.x; d < DC; d += 256) {
        float v = s[d] * inv * (1.0f + scale[d]);
        o[d] = __float2half_rn(v);
    }
}

// ---------------- rope + convert (fp16 qkv -> fp16 q,k,v) ----------------
__global__ void rope_split_kernel(const fp16* __restrict__ qkv, const int* __restrict__ positions,
                                  fp16* __restrict__ q, fp16* __restrict__ k, fp16* __restrict__ v)
{
    int row = blockIdx.x;
    float pos = (float)positions[row];
    const float QSCALE = 0.08838834764831845f;
    const fp16* src = qkv + (size_t)row * 4096;

    __shared__ float ssn[64], scs[64];
    if (threadIdx.x < 64) {
        int j = threadIdx.x;
        float ts = powf(10000.0f, (float)j * (1.0f / 64.0f));
        float sn, cs;
        sincosf(pos / ts, &sn, &cs);
        ssn[j] = sn; scs[j] = cs;
    }
    __syncthreads();

    for (int w = threadIdx.x; w < (NC + KC) * 64; w += 256) {
        int head = w >> 6;
        int j = w & 63;
        float sn = ssn[j], cs = scs[j];
        if (head < NC) {
            float x1 = __half2float(src[head * HC + j]);
            float x2 = __half2float(src[head * HC + j + 64]);
            size_t o = ((size_t)row * NC + head) * HC;
            q[o + j]      = __float2half_rn((x1 * cs - x2 * sn) * QSCALE);
            q[o + j + 64] = __float2half_rn((x2 * cs + x1 * sn) * QSCALE);
        } else {
            int kkh = head - NC;
            float x1 = __half2float(src[2048 + kkh * HC + j]);
            float x2 = __half2float(src[2048 + kkh * HC + j + 64]);
            size_t o = ((size_t)row * KC + kkh) * HC;
            k[o + j]      = __float2half_rn(x1 * cs - x2 * sn);
            k[o + j + 64] = __float2half_rn(x2 * cs + x1 * sn);
        }
    }
    for (int idx = threadIdx.x; idx < KHC; idx += 256) {
        size_t o = (size_t)row * KHC + idx;
        v[o] = src[3072 + idx];
    }
}

// ---------------- GEMM geometry ----------------
#define GBM 256
#define GBN 128
#define GBK 32
#define GSTAGES 5
#define ROWB   80
#define TILEA_B (256 * ROWB)                 // 20480
#define TILEW_B (128 * ROWB)                 // 10240
#define STAGE_F (TILEA_B + TILEW_B)          // 30720 (fp16 single)
#define TC_SMEM_F (GSTAGES * STAGE_F)        // 153600

// ---------------- fp16 single-pass GEMM (all projections) ----------------
// A single fp16, W single fp16 per stream (W0/W1 selected by stream i).
// epi: 0 plain fp32->C, 1 gelu->C, 2 +residual->C,
//      3 fused gate-up: cols alternate (gate,up); writes gelu(g)*u fp16 -> H16 (ld FC)
//      4 plain fp16 -> H16
// resmode: 0 per-stream R (R0/R1 + b*T0*ldC), 1 concat R0 (+ arow0*ldC)
// outmode: 0 concat rows, 1 stream-major rows
__global__ __launch_bounds__(512, 1)
void gemm_f16(const fp16* __restrict__ A_,
              const fp16* __restrict__ W0, const fp16* __restrict__ W1,
              float* __restrict__ C_, int Kd, int ldC, int epi,
              const float* __restrict__ R0, const float* __restrict__ R1,
              int resmode, int outmode,
              fp16* __restrict__ H16_)
{
    extern __shared__ char smem[];
    const uint32_t s0 = smem_to_u32(smem);

    const int tid = threadIdx.x;
    const int lane = tid & 31, warp = tid >> 5;
    const int wm = warp >> 2, wn = warp & 3;      // warp tile 64(m) x 32(n)

    const int z = blockIdx.z, i = z >> 1, b = z & 1;
    const size_t arow0 = (size_t)b * TOTC + (size_t)i * T0C;
    const fp16* A = A_ + arow0 * Kd;
    const fp16* W = i ? W1 : W0;
    float* C = (outmode == 0) ? (C_ + arow0 * (size_t)ldC)
                              : (C_ + ((size_t)i * BB * T0C + (size_t)b * T0C) * (size_t)ldC);
    const float* R = 0;
    if (epi == 2) R = (resmode == 0) ? ((i ? R1 : R0) + (size_t)b * T0C * ldC)
                                     : (R0 + arow0 * (size_t)ldC);
    fp16* H16 = 0;
    if (epi == 3) H16 = H16_ + arow0 * (size_t)FC;
    else if (epi == 4) H16 = H16_ + arow0 * (size_t)ldC;

    const int m0 = blockIdx.y * GBM, n0 = blockIdx.x * GBN;
    const int nk = Kd / GBK;

    // 1536 16B chunks per stage: A 1024, W 512. 3 per thread.
    #define ISSUE_STAGE_F(cc) do {                                               \
        int kk0 = (cc) * GBK;                                                    \
        uint32_t sbase = s0 + ((cc) % GSTAGES) * STAGE_F;                        \
        _Pragma("unroll")                                                        \
        for (int it = 0; it < 3; ++it) {                                         \
            int idx = tid + it * 512;                                            \
            const fp16* gp; uint32_t sa;                                         \
            if (idx < 1024) {                                                    \
                int row = idx >> 2, ch = idx & 3;                                \
                sa = sbase + row * ROWB + ch * 16;                               \
                gp = A + (size_t)(m0 + row) * Kd + kk0 + ch * 8;                 \
            } else {                                                             \
                int cid = idx - 1024;                                            \
                int row = cid >> 2, ch = cid & 3;                                \
                sa = sbase + TILEA_B + row * ROWB + ch * 16;                     \
                gp = W + (size_t)(n0 + row) * Kd + kk0 + ch * 8;                 \
            }                                                                    \
            CP_ASYNC16(sa, gp);                                                  \
        }                                                                        \
        CP_COMMIT();                                                             \
    } while (0)

    float acc[4][4][4];
    #pragma unroll
    for (int mf = 0; mf < 4; ++mf)
        #pragma unroll
        for (int nf = 0; nf < 4; ++nf)
            #pragma unroll
            for (int r = 0; r < 4; ++r) acc[mf][nf][r] = 0.f;

    const int a_row = wm * 64 + (lane & 15);
    const int a_cj  = lane >> 4;
    const int b_row = wn * 32 + (lane & 7) + ((lane >> 4) & 1) * 8;
    const int b_cj  = (lane >> 3) & 1;

    ISSUE_STAGE_F(0);
    ISSUE_STAGE_F(1);
    ISSUE_STAGE_F(2);
    ISSUE_STAGE_F(3);

    for (int c = 0; c < nk; ++c) {
        if (c + 3 < nk) CP_WAIT(3); else CP_WAIT(0);
        __syncthreads();

        uint32_t sbase = s0 + (c % GSTAGES) * STAGE_F;
        uint32_t aB = sbase, bB = sbase + TILEA_B;

        #pragma unroll
        for (int ks = 0; ks < 2; ++ks) {
            uint32_t aoff = (uint32_t)(a_row * ROWB + (ks * 2 + a_cj) * 16);
            uint32_t boff = (uint32_t)(b_row * ROWB + (ks * 2 + b_cj) * 16);

            uint32_t ah[4][4], bh[2][4];
            #pragma unroll
            for (int mf = 0; mf < 4; ++mf) LDSM4(ah[mf], aB + aoff + mf * (16 * ROWB));
            #pragma unroll
            for (int nf2 = 0; nf2 < 2; ++nf2) LDSM4(bh[nf2], bB + boff + nf2 * (16 * ROWB));

            #pragma unroll
            for (int nf2 = 0; nf2 < 2; ++nf2)
                #pragma unroll
                for (int mf = 0; mf < 4; ++mf) {
                    MMAF16(acc[mf][nf2 * 2],     ah[mf], bh[nf2][0], bh[nf2][1]);
                    MMAF16(acc[mf][nf2 * 2 + 1], ah[mf], bh[nf2][2], bh[nf2][3]);
                }

            if (ks == 0 && c + 4 < nk) ISSUE_STAGE_F(c + 4);
        }
    }

    #pragma unroll
    for (int mf = 0; mf < 4; ++mf) {
        int r0 = m0 + wm * 64 + mf * 16 + (lane >> 2);
        #pragma unroll
        for (int nf = 0; nf < 4; ++nf) {
            int col = n0 + wn * 32 + nf * 8 + (lane & 3) * 2;
            float2 v0 = make_float2(acc[mf][nf][0], acc[mf][nf][1]);
            float2 v1 = make_float2(acc[mf][nf][2], acc[mf][nf][3]);
            if (epi == 3) {
                // cols alternate (gate, up): v.x = gate_j, v.y = up_j, j = col>>1
                int gcol = col >> 1;
                H16[(size_t)r0 * FC + gcol]       = __float2half_rn(gelu_tanh(v0.x) * v0.y);
                H16[(size_t)(r0 + 8) * FC + gcol] = __float2half_rn(gelu_tanh(v1.x) * v1.y);
            } else if (epi == 4) {
                *(uint32_t*)((char*)H16 + ((size_t)r0 * ldC + col) * 2)       = pack2h(v0.x, v0.y);
                *(uint32_t*)((char*)H16 + ((size_t)(r0 + 8) * ldC + col) * 2) = pack2h(v1.x, v1.y);
            } else {
                if (epi == 1) {
                    v0.x = gelu_tanh(v0.x); v0.y = gelu_tanh(v0.y);
                    v1.x = gelu_tanh(v1.x); v1.y = gelu_tanh(v1.y);
                } else if (epi == 2) {
                    float2 ra = *(const float2*)(R + (size_t)r0 * ldC + col);
                    float2 rb = *(const float2*)(R + (size_t)(r0 + 8) * ldC + col);
                    v0.x += ra.x; v0.y += ra.y;
                    v1.x += rb.x; v1.y += rb.y;
                }
                *(float2*)(C + (size_t)r0 * ldC + col)       = v0;
                *(float2*)(C + (size_t)(r0 + 8) * ldC + col) = v1;
            }
        }
    }
}

// ---------------- attention: single-fp16 flash kernel ----------------
#define ATT_BM 128
#define ATT_BN 32
#define QROWB 272
#define KROWB 272
#define PROWB 80
#define SQ 0
#define SKV 34816
#define KVTILE 8704
#define SP 69632
#define ATT_SMEM 79872
#define NEGA (-1e30f)

__global__ __launch_bounds__(256, 1)
void attn_mma_kernel(const fp16* __restrict__ q, const fp16* __restrict__ k,
                     const fp16* __restrict__ v, fp16* __restrict__ enc)
{
    extern __shared__ char smem[];
    const uint32_t s0u = smem_to_u32(smem);
    const int tid = threadIdx.x, lane = tid & 31, w = tid >> 5;
    const int bq = blockIdx.z;
    const int n = blockIdx.y;
    const int kk = n >> 1;
    const int t0 = ((int)gridDim.x - 1 - (int)blockIdx.x) * ATT_BM;
    const size_t bT = (size_t)bq * TOTC;

    // Q tile: 128 rows x 128 fp16 = 2048 16B chunks
    #pragma unroll
    for (int it = 0; it < 8; ++it) {
        int idx = tid + it * 256;
        int row = idx >> 4, ch = idx & 15;
        const fp16* src = q + ((bT + t0 + row) * NC + n) * HC + ch * 8;
        CP_ASYNC16(s0u + SQ + row * QROWB + ch * 16, src);
    }
    CP_COMMIT();

    #define LOAD_KV(j) do {                                                        \
        int _bf = (j) & 1; int _s0 = (j) * ATT_BN;                                 \
        _Pragma("unroll")                                                          \
        for (int it = 0; it < 4; ++it) {                                           \
            int idx = tid + it * 256;                                              \
            int tt = idx >> 9, cid = idx & 511, row = cid >> 4, ch = cid & 15;     \
            const fp16* srcp = (tt ? v : k) + ((bT + _s0 + row) * KC + kk) * HC + ch * 8; \
            CP_ASYNC16(s0u + SKV + (_bf * 2 + tt) * KVTILE + row * KROWB + ch * 16, srcp); \
        }                                                                          \
        CP_COMMIT();                                                               \
    } while (0)

    const int nb = t0 / ATT_BN + 4;
    LOAD_KV(0);

    const int tw = t0 + w * 16;
    const int r0 = lane >> 2;
    float oacc[16][4];
    #pragma unroll
    for (int a = 0; a < 16; ++a) { oacc[a][0] = oacc[a][1] = oacc[a][2] = oacc[a][3] = 0.f; }
    float mrow0 = NEGA, mrow1 = NEGA, lrow0 = 0.f, lrow1 = 0.f;

    const uint32_t ps_base = s0u + SP + (w * 16) * PROWB;

    for (int j = 0; j < nb; ++j) {
        CP_WAIT(0);
        __syncthreads();
        if (j + 1 < nb) LOAD_KV(j + 1);

        const int sblk = j * ATT_BN;
        const int bf = j & 1;
        const uint32_t kB = s0u + SKV + (bf * 2 + 0) * KVTILE;
        const uint32_t vB = s0u + SKV + (bf * 2 + 1) * KVTILE;

        if (sblk <= tw + 15) {
            float sacc[4][4];
            #pragma unroll
            for (int nf = 0; nf < 4; ++nf) { sacc[nf][0]=sacc[nf][1]=sacc[nf][2]=sacc[nf][3]=0.f; }
            const uint32_t aoff_base = (uint32_t)((w * 16 + (lane & 15)) * QROWB + (lane >> 4) * 16);
            const uint32_t brow = (uint32_t)((lane & 7) + ((lane >> 4) & 1) * 8);
            const uint32_t bco  = (uint32_t)(((lane >> 3) & 1) * 16);
            #pragma unroll
            for (int ks = 0; ks < 8; ++ks) {
                uint32_t ah[4], bh0[4], bh1[4];
                uint32_t aoff = aoff_base + ks * 32;
                LDSM4(ah, s0u + SQ + aoff);
                uint32_t boff0 = brow * KROWB + ks * 32 + bco;
                uint32_t boff1 = boff0 + 16 * KROWB;
                LDSM4(bh0, kB + boff0); LDSM4(bh1, kB + boff1);
                MMAF16(sacc[0], ah, bh0[0], bh0[1]);
                MMAF16(sacc[1], ah, bh0[2], bh0[3]);
                MMAF16(sacc[2], ah, bh1[0], bh1[1]);
                MMAF16(sacc[3], ah, bh1[2], bh1[3]);
            }

            if (sblk + ATT_BN - 1 > tw) {
                #pragma unroll
                for (int nf = 0; nf < 4; ++nf) {
                    int sg = sblk + nf * 8 + (lane & 3) * 2;
                    int tg0 = tw + r0, tg1 = tg0 + 8;
                    if (sg     > tg0) sacc[nf][0] = NEGA;
                    if (sg + 1 > tg0) sacc[nf][1] = NEGA;
                    if (sg     > tg1) sacc[nf][2] = NEGA;
                    if (sg + 1 > tg1) sacc[nf][3] = NEGA;
                }
            }

            float mx0 = NEGA, mx1 = NEGA;
            #pragma unroll
            for (int nf = 0; nf < 4; ++nf) {
                mx0 = fmaxf(mx0, fmaxf(sacc[nf][0], sacc[nf][1]));
                mx1 = fmaxf(mx1, fmaxf(sacc[nf][2], sacc[nf][3]));
            }
            mx0 = fmaxf(mx0, __shfl_xor_sync(0xffffffffu, mx0, 1));
            mx0 = fmaxf(mx0, __shfl_xor_sync(0xffffffffu, mx0, 2));
            mx1 = fmaxf(mx1, __shfl_xor_sync(0xffffffffu, mx1, 1));
            mx1 = fmaxf(mx1, __shfl_xor_sync(0xffffffffu, mx1, 2));
            float mn0 = fmaxf(mrow0, mx0), mn1 = fmaxf(mrow1, mx1);
            float al0 = __expf(mrow0 - mn0), al1 = __expf(mrow1 - mn1);
            float se0 = 0.f, se1 = 0.f;
            #pragma unroll
            for (int nf = 0; nf < 4; ++nf) {
                float p0 = __expf(sacc[nf][0] - mn0);
                float p1 = __expf(sacc[nf][1] - mn0);
                float p2 = __expf(sacc[nf][2] - mn1);
                float p3 = __expf(sacc[nf][3] - mn1);
                se0 += p0 + p1; se1 += p2 + p3;
                uint32_t pcol = (uint32_t)((nf * 8 + (lane & 3) * 2) * 2);
                *(uint32_t*)(smem + (ps_base - s0u) + r0 * PROWB + pcol)       = pack2h(p0, p1);
                *(uint32_t*)(smem + (ps_base - s0u) + (r0 + 8) * PROWB + pcol) = pack2h(p2, p3);
            }
            se0 += __shfl_xor_sync(0xffffffffu, se0, 1);
            se0 += __shfl_xor_sync(0xffffffffu, se0, 2);
            se1 += __shfl_xor_sync(0xffffffffu, se1, 1);
            se1 += __shfl_xor_sync(0xffffffffu, se1, 2);
            mrow0 = mn0; mrow1 = mn1;
            lrow0 = lrow0 * al0 + se0;
            lrow1 = lrow1 * al1 + se1;
            #pragma unroll
            for (int a = 0; a < 16; ++a) {
                oacc[a][0] *= al0; oacc[a][1] *= al0;
                oacc[a][2] *= al1; oacc[a][3] *= al1;
            }
            __syncwarp();

            const uint32_t vrow = (uint32_t)((lane & 7) + ((lane >> 3) & 1) * 8);
            const uint32_t vco  = (uint32_t)((lane >> 4) * 16);
            #pragma unroll
            for (int ks2 = 0; ks2 < 2; ++ks2) {
                uint32_t ph[4];
                uint32_t pa = (uint32_t)((lane & 15) * PROWB + (ks2 * 16 + (lane >> 4) * 8) * 2);
                LDSM4(ph, ps_base + pa);
                #pragma unroll
                for (int hf = 0; hf < 8; ++hf) {
                    uint32_t bvh[4];
                    uint32_t voff = (ks2 * 16 + vrow) * KROWB + hf * 32 + vco;
                    LDSM4T(bvh, vB + voff);
                    MMAF16(oacc[2*hf],     ph, bvh[0], bvh[1]);
                    MMAF16(oacc[2*hf + 1], ph, bvh[2], bvh[3]);
                }
            }
        }
    }

    float inv0 = 1.0f / lrow0, inv1 = 1.0f / lrow1;
    #pragma unroll
    for (int nt = 0; nt < 16; ++nt) {
        int hcol = nt * 8 + (lane & 3) * 2;
        size_t o0 = ((bT + tw + r0) * NC + n) * HC + hcol;
        size_t o1 = ((bT + tw + r0 + 8) * NC + n) * HC + hcol;
        *(uint32_t*)((char*)enc + o0 * 2) = pack2h(oacc[nt][0] * inv0, oacc[nt][1] * inv0);
        *(uint32_t*)((char*)enc + o1 * 2) = pack2h(oacc[nt][2] * inv1, oacc[nt][3] * inv1);
    }
}

// ---------------- host ----------------
extern "C" void kernel_launch(void* const* d_in, const int* in_sizes, int n_in,
                              void* d_out, int out_size)
{
    (void)in_sizes; (void)n_in; (void)out_size;
    const float* x0  = (const float*)d_in[0];
    const float* x1  = (const float*)d_in[1];
    const int*   pos = (const int*)  d_in[2];
    const float* q0w = (const float*)d_in[4];
    const float* q1w = (const float*)d_in[5];
    const float* k0w = (const float*)d_in[6];
    const float* k1w = (const float*)d_in[7];
    const float* v0w = (const float*)d_in[8];
    const float* v1w = (const float*)d_in[9];
    const float* o0w = (const float*)d_in[10];
    const float* o1w = (const float*)d_in[11];
    const float* gt0 = (const float*)d_in[12];
    const float* gt1 = (const float*)d_in[13];
    const float* up0 = (const float*)d_in[14];
    const float* up1 = (const float*)d_in[15];
    const float* dw0 = (const float*)d_in[16];
    const float* dw1 = (const float*)d_in[17];
    const float* pa0 = (const float*)d_in[18];
    const float* pa1 = (const float*)d_in[19];
    const float* pf0 = (const float*)d_in[20];
    const float* pf1 = (const float*)d_in[21];
    float* out = (float*)d_out;

    float *res;
    fp16 *qkvh, *qb, *kb, *vb, *pre, *enc, *hid, *gu, *wf;
    cudaGetSymbolAddress((void**)&res,  g_res);
    cudaGetSymbolAddress((void**)&qkvh, g_qkvh);
    cudaGetSymbolAddress((void**)&qb,   g_q);
    cudaGetSymbolAddress((void**)&kb,   g_k);
    cudaGetSymbolAddress((void**)&vb,   g_v);
    cudaGetSymbolAddress((void**)&pre,  g_pre);
    cudaGetSymbolAddress((void**)&enc,  g_enc);
    cudaGetSymbolAddress((void**)&hid,  g_hid);
    cudaGetSymbolAddress((void**)&gu,   g_gu);
    cudaGetSymbolAddress((void**)&wf,   g_wf);

    cudaFuncSetAttribute(gemm_f16, cudaFuncAttributeMaxDynamicSharedMemorySize, TC_SMEM_F);
    cudaFuncSetAttribute(attn_mma_kernel, cudaFuncAttributeMaxDynamicSharedMemorySize, ATT_SMEM);

    const size_t QN   = (size_t)NHC * DC;     // 4194304
    const size_t KN   = (size_t)KHC * DC;     // 2097152
    const size_t FN   = (size_t)FC * DC;      // 16777216
    const size_t QKVN = QN + 2 * KN;          // 8388608
    const size_t oqkv0 = 0, oqkv1 = QKVN;
    const size_t oo0  = 2 * QKVN,   oo1  = oo0 + QN;
    const size_t ogu0 = oo1 + QN,   ogu1 = ogu0 + 2 * FN;   // interleaved gate|up
    const size_t od0  = ogu1 + 2 * FN, od1 = od0 + FN;

    // [launch 0] all weight conversions -> fp16 (gate/up row-interleaved)
    {
        CvtF16Jobs J;
        const float* srcs[NJOBS] = {q0w, k0w, v0w, q1w, k1w, v1w, o0w, o1w,
                                    gt0, up0, gt1, up1, dw0, dw1};
        const size_t offs[NJOBS] = {oqkv0, oqkv0 + QN, oqkv0 + QN + KN,
                                    oqkv1, oqkv1 + QN, oqkv1 + QN + KN,
                                    oo0, oo1, ogu0, ogu0, ogu1, ogu1, od0, od1};
        const size_t lens[NJOBS] = {QN, KN, KN, QN, KN, KN, QN, QN,
                                    FN, FN, FN, FN, FN, FN};
        const int    ilvs[NJOBS] = {0,0,0,0,0,0,0,0, 1,2,1,2, 0,0};
        int blk = 0;
        for (int j = 0; j < NJOBS; ++j) {
            J.src[j] = srcs[j];
            J.dst[j] = wf + offs[j];
            J.ilv[j] = ilvs[j];
            J.startblk[j] = blk;
            blk += (int)(lens[j] / 8192);
        }
        J.startblk[NJOBS] = blk;
        cvt_f16_kernel<<<blk, 256>>>(J);
    }

    // [launch 1] pre-attn rmsnorm -> fp16
    {
        dim3 g(BB * T0C, 2);
        rmsnorm2_f16_kernel<<<g, 256>>>(x0, x1, pre, pa0, pa1, 0);
    }

    // [launches 2-3] QKV projection (Q half, KV half) -> fp16 qkvh (profiled slot)
    {
        dim3 gq(2048 / GBN, T0C / GBM, 4);
        gemm_f16<<<gq, 512, TC_SMEM_F>>>(pre, wf + oqkv0, wf + oqkv1,
                                         0, DC, 4096, 4, 0, 0, 0, 0, qkvh);
        gemm_f16<<<gq, 512, TC_SMEM_F>>>(pre, wf + oqkv0 + QN, wf + oqkv1 + QN,
                                         0, DC, 4096, 4, 0, 0, 0, 0, qkvh + 2048);
    }

    // [launch 4] RoPE + scale -> fp16 q,k,v
    rope_split_kernel<<<BB * TOTC, 256>>>(qkvh, pos, qb, kb, vb);

    // [launch 5] attention -> fp16 enc
    {
        dim3 ga(TOTC / ATT_BM, NC, BB);
        attn_mma_kernel<<<ga, 256, ATT_SMEM>>>(qb, kb, vb, enc);
    }

    // [launch 6] O projection + residual (per-stream x) -> fp32 res
    {
        dim3 go(DC / GBN, T0C / GBM, 4);
        gemm_f16<<<go, 512, TC_SMEM_F>>>(enc, wf + oo0, wf + oo1,
                                         res, NHC, DC, 2, x0, x1, 0, 0, 0);
    }

    // [launch 7] pre-ffw rmsnorm -> fp16 (concat src)
    {
        dim3 g(BB * T0C, 2);
        rmsnorm2_f16_kernel<<<g, 256>>>(res, res, hid, pf0, pf1, 1);
    }

    // [launch 8] fused gate-up projection (interleaved W) -> gu fp16
    {
        dim3 gf(16384 / GBN, T0C / GBM, 4);
        gemm_f16<<<gf, 512, TC_SMEM_F>>>(hid, wf + ogu0, wf + ogu1,
                                         0, DC, 16384, 3, 0, 0, 0, 0, gu);
    }

    // [launch 9] down projection + residual (concat res) -> out (stream-major)
    {
        dim3 gd(DC / GBN, T0C / GBM, 4);
        gemm_f16<<<gd, 512, TC_SMEM_F>>>(gu, wf + od0, wf + od1,
                                         out, FC, DC, 2, res, 0, 1, 1, 0);
    }
}